// round 8
// baseline (speedup 1.0000x reference)
#include <cuda_runtime.h>
#include <cuda_bf16.h>
#include <cstdint>
#include <cstddef>

// Problem constants
#define B_  16
#define S_  512
#define D_  1024
#define H_  16
#define DH_ 64
#define M_  (B_ * S_)   // 8192

// ---------------------------------------------------------------------------
// Scratch (static device globals)
// ---------------------------------------------------------------------------
__device__ __align__(128) __nv_bfloat16 g_Ah[M_ * D_];   // v-split, later attn out (row-major)
__device__ __align__(128) __nv_bfloat16 g_Al[M_ * D_];
__device__ __align__(128) __nv_bfloat16 g_Bh[D_ * D_];   // W^T hi  [N][K]
__device__ __align__(128) __nv_bfloat16 g_Bl[D_ * D_];
__device__ __align__(128) __nv_bfloat16 g_Qh[M_ * D_];   // head-major [b,h,s,dh]
__device__ __align__(128) __nv_bfloat16 g_Ql[M_ * D_];
__device__ __align__(128) __nv_bfloat16 g_Kh[M_ * D_];
__device__ __align__(128) __nv_bfloat16 g_Kl[M_ * D_];
__device__ __align__(128) __nv_bfloat16 g_Vh[M_ * D_];
__device__ __align__(128) __nv_bfloat16 g_Vl[M_ * D_];

// ---------------------------------------------------------------------------
// PTX helpers (sm_80+ features only; compute_103 lowering rejects sm_103a-only)
// ---------------------------------------------------------------------------
__device__ __forceinline__ uint32_t smem_u32(const void* p) {
    uint32_t a;
    asm("{ .reg .u64 t; cvta.to.shared.u64 t, %1; cvt.u32.u64 %0, t; }" : "=r"(a) : "l"(p));
    return a;
}
__device__ __forceinline__ void cp16(uint32_t saddr, const void* gaddr) {
    asm volatile("cp.async.cg.shared.global [%0], [%1], 16;" :: "r"(saddr), "l"(gaddr) : "memory");
}
#define CP_COMMIT() asm volatile("cp.async.commit_group;" ::: "memory")
#define CP_WAIT0()  asm volatile("cp.async.wait_group 0;" ::: "memory")
#define CP_WAIT1()  asm volatile("cp.async.wait_group 1;" ::: "memory")
#define CP_WAIT2()  asm volatile("cp.async.wait_group 2;" ::: "memory")

__device__ __forceinline__ void ldsm4(uint32_t* r, uint32_t a) {
    asm volatile("ldmatrix.sync.aligned.m8n8.x4.shared.b16 {%0,%1,%2,%3}, [%4];"
                 : "=r"(r[0]), "=r"(r[1]), "=r"(r[2]), "=r"(r[3]) : "r"(a));
}
__device__ __forceinline__ void ldsm4t(uint32_t* r, uint32_t a) {
    asm volatile("ldmatrix.sync.aligned.m8n8.x4.trans.shared.b16 {%0,%1,%2,%3}, [%4];"
                 : "=r"(r[0]), "=r"(r[1]), "=r"(r[2]), "=r"(r[3]) : "r"(a));
}
__device__ __forceinline__ void mma16816(float* c, const uint32_t* a, const uint32_t* b) {
    asm volatile(
        "mma.sync.aligned.m16n8k16.row.col.f32.bf16.bf16.f32 "
        "{%0,%1,%2,%3}, {%4,%5,%6,%7}, {%8,%9}, {%0,%1,%2,%3};"
        : "+f"(c[0]), "+f"(c[1]), "+f"(c[2]), "+f"(c[3])
        : "r"(a[0]), "r"(a[1]), "r"(a[2]), "r"(a[3]), "r"(b[0]), "r"(b[1]));
}

#define SMEM_SWZ(o) ((o) ^ (((o) >> 3) & 0x70))

// ---------------------------------------------------------------------------
// HMMA GEMM: C = Ah@Bh^T + Ah@Bl^T + Al@Bh^T (+bias)
// MODE 0: fp32 row-major C.  MODE 1: split bf16 head-major [b,h,s,dh].
// SKIP: early-exit CTAs whose rows are never read by attention (K/V proj).
// CTA tile 128x128, BK=64, 3-stage cp.async; 8 warps 2x4, warp tile 64x32.
// MMA issue order is term-major: accumulator reuse distance 16 (hides HMMA RAW).
// ---------------------------------------------------------------------------
#define T_AH 0
#define T_AL 16384
#define T_BH 32768
#define T_BL 49152
#define STAGE_BYTES 65536
#define GEMM_SMEM (3 * STAGE_BYTES)   // 196608

__device__ __forceinline__ void load_tile16(uint32_t sdst, const __nv_bfloat16* g,
                                            int row0, int kc, int tid) {
#pragma unroll
    for (int i = 0; i < 4; i++) {
        int idx = tid + i * 256;
        int r = idx >> 3, c = idx & 7;
        const __nv_bfloat16* gp = g + (size_t)(row0 + r) * D_ + kc * 64 + c * 8;
        cp16(sdst + SMEM_SWZ(r * 128 + c * 16), gp);
    }
}

template <int MODE, bool SKIP>
__global__ __launch_bounds__(256) void gemm_mma(
    const __nv_bfloat16* __restrict__ Ah, const __nv_bfloat16* __restrict__ Al,
    const __nv_bfloat16* __restrict__ Bh, const __nv_bfloat16* __restrict__ Bl,
    const float* __restrict__ bias, float* __restrict__ C,
    __nv_bfloat16* __restrict__ Ch, __nv_bfloat16* __restrict__ Cl,
    const int* __restrict__ lengths)
{
    extern __shared__ __align__(1024) char smem[];
    const int tid  = threadIdx.x;
    const int wid  = tid >> 5, lane = tid & 31;
    const int m0   = blockIdx.y * 128;
    const int n0   = blockIdx.x * 128;

    if (SKIP) {
        // attention reads rows [0, ceil(len/64)*64) of each batch's K/V slab
        int len = lengths[m0 >> 9];
        if ((m0 & 511) >= ((len + 63) & ~63)) return;
    }

    const int wm   = (wid >> 2) * 64;
    const int wn   = (wid & 3)  * 32;
    uint32_t sb = smem_u32(smem);

    float acc[4][4][4];
#pragma unroll
    for (int i = 0; i < 4; i++)
#pragma unroll
        for (int j = 0; j < 4; j++)
#pragma unroll
            for (int k = 0; k < 4; k++) acc[i][j][k] = 0.f;

    const int a_row = wm + (lane & 15);
    const int a_coff = (lane >> 4) * 16;
    const int b_row = wn + ((lane >> 4) << 3) + (lane & 7);
    const int b_coff = ((lane >> 3) & 1) * 16;

    // prologue: chunks 0,1 -> stages 0,1
#pragma unroll
    for (int p = 0; p < 2; p++) {
        uint32_t so = sb + p * STAGE_BYTES;
        load_tile16(so + T_AH, Ah, m0, p, tid);
        load_tile16(so + T_AL, Al, m0, p, tid);
        load_tile16(so + T_BH, Bh, n0, p, tid);
        load_tile16(so + T_BL, Bl, n0, p, tid);
        CP_COMMIT();
    }

    int stage = 0, nstage = 2;
#pragma unroll 1
    for (int c = 0; c < 16; c++) {
        if (c + 2 < 16) {
            uint32_t so = sb + nstage * STAGE_BYTES;
            load_tile16(so + T_AH, Ah, m0, c + 2, tid);
            load_tile16(so + T_AL, Al, m0, c + 2, tid);
            load_tile16(so + T_BH, Bh, n0, c + 2, tid);
            load_tile16(so + T_BL, Bl, n0, c + 2, tid);
            CP_COMMIT();
            CP_WAIT2();
        } else if (c + 1 < 16) {
            CP_WAIT1();
        } else {
            CP_WAIT0();
        }
        __syncthreads();

        const uint32_t so = sb + stage * STAGE_BYTES;
#pragma unroll
        for (int ks = 0; ks < 4; ks++) {
            const int kb = ks * 32;
            uint32_t ah[4][4], al[4][4], bh[2][4], bl[2][4];
#pragma unroll
            for (int mt = 0; mt < 4; mt++) {
                uint32_t off = SMEM_SWZ((a_row + mt * 16) * 128 + kb + a_coff);
                ldsm4(ah[mt], so + T_AH + off);
                ldsm4(al[mt], so + T_AL + off);
            }
#pragma unroll
            for (int nt2 = 0; nt2 < 2; nt2++) {
                uint32_t off = SMEM_SWZ((b_row + nt2 * 16) * 128 + kb + b_coff);
                ldsm4(bh[nt2], so + T_BH + off);
                ldsm4(bl[nt2], so + T_BL + off);
            }
            // term-major: consecutive MMAs hit different accumulators (dist 16)
#pragma unroll
            for (int mt = 0; mt < 4; mt++)
#pragma unroll
                for (int nt = 0; nt < 4; nt++)
                    mma16816(acc[mt][nt], ah[mt], &bh[nt >> 1][(nt & 1) * 2]);
#pragma unroll
            for (int mt = 0; mt < 4; mt++)
#pragma unroll
                for (int nt = 0; nt < 4; nt++)
                    mma16816(acc[mt][nt], ah[mt], &bl[nt >> 1][(nt & 1) * 2]);
#pragma unroll
            for (int mt = 0; mt < 4; mt++)
#pragma unroll
                for (int nt = 0; nt < 4; nt++)
                    mma16816(acc[mt][nt], al[mt], &bh[nt >> 1][(nt & 1) * 2]);
        }
        __syncthreads();
        stage = (stage + 1) == 3 ? 0 : stage + 1;
        nstage = (nstage + 1) == 3 ? 0 : nstage + 1;
    }

    const int er = lane >> 2;
    const int ec = (lane & 3) * 2;
#pragma unroll
    for (int mt = 0; mt < 4; mt++) {
#pragma unroll
        for (int nt = 0; nt < 4; nt++) {
            int row = m0 + wm + mt * 16 + er;
            int col = n0 + wn + nt * 8 + ec;
            float b0 = bias[col], b1 = bias[col + 1];
            float o0 = acc[mt][nt][0] + b0, o1 = acc[mt][nt][1] + b1;
            float o2 = acc[mt][nt][2] + b0, o3 = acc[mt][nt][3] + b1;
            if (MODE == 0) {
                float2 p0 = make_float2(o0, o1), p1 = make_float2(o2, o3);
                *(float2*)(C + (size_t)row * D_ + col) = p0;
                *(float2*)(C + (size_t)(row + 8) * D_ + col) = p1;
            } else {
                int bb = row >> 9, ss = row & 511, hh = col >> 6, dd = col & 63;
                size_t base = (((size_t)bb * H_ + hh) * S_ + ss) * DH_ + dd;
                __nv_bfloat162 hp = __floats2bfloat162_rn(o0, o1);
                float2 hf = __bfloat1622float2(hp);
                __nv_bfloat162 lp = __floats2bfloat162_rn(o0 - hf.x, o1 - hf.y);
                *(__nv_bfloat162*)(Ch + base) = hp;
                *(__nv_bfloat162*)(Cl + base) = lp;
                __nv_bfloat162 hp2 = __floats2bfloat162_rn(o2, o3);
                float2 hf2 = __bfloat1622float2(hp2);
                __nv_bfloat162 lp2 = __floats2bfloat162_rn(o2 - hf2.x, o3 - hf2.y);
                *(__nv_bfloat162*)(Ch + base + 8 * DH_) = hp2;
                *(__nv_bfloat162*)(Cl + base + 8 * DH_) = lp2;
            }
        }
    }
}

// ---------------------------------------------------------------------------
// HMMA flash attention.
// CTA = one (b,h) x 128 q rows. 8 warps x 16 rows. 64-key tiles, 2-stage.
// 3-term split; term-major MMA issue (acc reuse distance 8).
// Writes split bf16 row-major [M][D] for the O projection.
// ---------------------------------------------------------------------------
#define AQ_H 0
#define AQ_L 16384
#define AST  32768
#define AK_H 0
#define AK_L 8192
#define AV_H 16384
#define AV_L 24576
#define AST_BYTES 32768
#define ATTN_SMEM (32768 + 2 * AST_BYTES)   // 98304

__global__ __launch_bounds__(256) void attn_mma(
    const __nv_bfloat16* __restrict__ Qh_, const __nv_bfloat16* __restrict__ Ql_,
    const __nv_bfloat16* __restrict__ Kh_, const __nv_bfloat16* __restrict__ Kl_,
    const __nv_bfloat16* __restrict__ Vh_, const __nv_bfloat16* __restrict__ Vl_,
    const int* __restrict__ lengths,
    __nv_bfloat16* __restrict__ Oh_, __nv_bfloat16* __restrict__ Ol_)
{
    extern __shared__ __align__(1024) char smem[];
    const int tid = threadIdx.x, wid = tid >> 5, lane = tid & 31;
    const int b = blockIdx.z, h = blockIdx.y, q0 = blockIdx.x * 128;
    const int len = lengths[b];
    uint32_t sb = smem_u32(smem);
    const size_t bh_off = ((size_t)b * H_ + h) * (S_ * DH_);

    // Q tile load (128 rows x 128B, hi+lo)
#pragma unroll
    for (int i = 0; i < 4; i++) {
        int idx = tid + i * 256;
        int r = idx >> 3, c = idx & 7;
        cp16(sb + AQ_H + SMEM_SWZ(r * 128 + c * 16), Qh_ + bh_off + (size_t)(q0 + r) * DH_ + c * 8);
        cp16(sb + AQ_L + SMEM_SWZ(r * 128 + c * 16), Ql_ + bh_off + (size_t)(q0 + r) * DH_ + c * 8);
    }
    CP_COMMIT();

    const int jend = (len + 63) & ~63;     // <= 512
    const int ntile = jend >> 6;

    // prefetch KV tile 0 -> stage 0
    {
        uint32_t so = sb + AST;
#pragma unroll
        for (int i = 0; i < 2; i++) {
            int idx = tid + i * 256;
            int r = idx >> 3, c = idx & 7;
            size_t g = bh_off + (size_t)r * DH_ + c * 8;
            uint32_t sw = SMEM_SWZ(r * 128 + c * 16);
            cp16(so + AK_H + sw, Kh_ + g);
            cp16(so + AK_L + sw, Kl_ + g);
            cp16(so + AV_H + sw, Vh_ + g);
            cp16(so + AV_L + sw, Vl_ + g);
        }
        CP_COMMIT();
    }

    // wait for Q (KV0 may still fly), then pull Q fragments
    CP_WAIT1();
    __syncthreads();

    const int a_row = wid * 16 + (lane & 15);
    const int a_co = (lane >> 4) * 16;
    uint32_t qh[4][4], ql[4][4];
#pragma unroll
    for (int s = 0; s < 4; s++) {
        uint32_t off = SMEM_SWZ(a_row * 128 + s * 32 + a_co);
        ldsm4(qh[s], sb + AQ_H + off);
        ldsm4(ql[s], sb + AQ_L + off);
    }

    float oa[8][4];
#pragma unroll
    for (int i = 0; i < 8; i++)
#pragma unroll
        for (int j = 0; j < 4; j++) oa[i][j] = 0.f;
    float m0 = -1e30f, m1 = -1e30f, l0 = 0.f, l1 = 0.f;

    const int krow = ((lane >> 4) << 3) + (lane & 7);   // K ldsm pattern (gemm-B)
    const int kco  = ((lane >> 3) & 1) * 16;
    const int vrow = lane & 15;                          // V trans ldsm pattern
    const int vco  = (lane >> 4) * 16;

#pragma unroll 1
    for (int t = 0; t < ntile; t++) {
        CP_WAIT0();
        __syncthreads();
        if (t + 1 < ntile) {
            uint32_t so = sb + AST + ((t + 1) & 1) * AST_BYTES;
            int j0n = (t + 1) * 64;
#pragma unroll
            for (int i = 0; i < 2; i++) {
                int idx = tid + i * 256;
                int r = idx >> 3, c = idx & 7;
                size_t g = bh_off + (size_t)(j0n + r) * DH_ + c * 8;
                uint32_t sw = SMEM_SWZ(r * 128 + c * 16);
                cp16(so + AK_H + sw, Kh_ + g);
                cp16(so + AK_L + sw, Kl_ + g);
                cp16(so + AV_H + sw, Vh_ + g);
                cp16(so + AV_L + sw, Vl_ + g);
            }
            CP_COMMIT();
        }

        const uint32_t so = sb + AST + (t & 1) * AST_BYTES;
        const int j0 = t * 64;

        // ---- S = Q @ K^T (3-term split, term-major issue) ----
        float S[8][4];
#pragma unroll
        for (int i = 0; i < 8; i++)
#pragma unroll
            for (int j = 0; j < 4; j++) S[i][j] = 0.f;
#pragma unroll
        for (int s = 0; s < 4; s++) {
            uint32_t kh4[4][4], kl4[4][4];
#pragma unroll
            for (int g = 0; g < 4; g++) {
                uint32_t off = SMEM_SWZ((g * 16 + krow) * 128 + s * 32 + kco);
                ldsm4(kh4[g], so + AK_H + off);
                ldsm4(kl4[g], so + AK_L + off);
            }
#pragma unroll
            for (int g = 0; g < 4; g++) {
                mma16816(S[2 * g],     qh[s], kh4[g]);
                mma16816(S[2 * g + 1], qh[s], kh4[g] + 2);
            }
#pragma unroll
            for (int g = 0; g < 4; g++) {
                mma16816(S[2 * g],     qh[s], kl4[g]);
                mma16816(S[2 * g + 1], qh[s], kl4[g] + 2);
            }
#pragma unroll
            for (int g = 0; g < 4; g++) {
                mma16816(S[2 * g],     ql[s], kh4[g]);
                mma16816(S[2 * g + 1], ql[s], kh4[g] + 2);
            }
        }

        // ---- scale + mask ----
        if (j0 + 64 > len) {
            int kb0 = j0 + 2 * (lane & 3);
#pragma unroll
            for (int j = 0; j < 8; j++) {
#pragma unroll
                for (int e = 0; e < 4; e++) {
                    int kk = kb0 + 8 * j + (e & 1);
                    S[j][e] = (kk < len) ? S[j][e] * 0.125f : -1e9f;
                }
            }
        } else {
#pragma unroll
            for (int j = 0; j < 8; j++)
#pragma unroll
                for (int e = 0; e < 4; e++) S[j][e] *= 0.125f;
        }

        // ---- online softmax ----
        float mx0 = -1e30f, mx1 = -1e30f;
#pragma unroll
        for (int j = 0; j < 8; j++) {
            mx0 = fmaxf(mx0, fmaxf(S[j][0], S[j][1]));
            mx1 = fmaxf(mx1, fmaxf(S[j][2], S[j][3]));
        }
        mx0 = fmaxf(mx0, __shfl_xor_sync(0xffffffffu, mx0, 1));
        mx0 = fmaxf(mx0, __shfl_xor_sync(0xffffffffu, mx0, 2));
        mx1 = fmaxf(mx1, __shfl_xor_sync(0xffffffffu, mx1, 1));
        mx1 = fmaxf(mx1, __shfl_xor_sync(0xffffffffu, mx1, 2));
        float mn0 = fmaxf(m0, mx0), mn1 = fmaxf(m1, mx1);
        float f0 = __expf(m0 - mn0), f1 = __expf(m1 - mn1);
        l0 *= f0; l1 *= f1;
#pragma unroll
        for (int i = 0; i < 8; i++) {
            oa[i][0] *= f0; oa[i][1] *= f0; oa[i][2] *= f1; oa[i][3] *= f1;
        }
        float rs0 = 0.f, rs1 = 0.f;
#pragma unroll
        for (int j = 0; j < 8; j++) {
            S[j][0] = __expf(S[j][0] - mn0);
            S[j][1] = __expf(S[j][1] - mn0);
            S[j][2] = __expf(S[j][2] - mn1);
            S[j][3] = __expf(S[j][3] - mn1);
            rs0 += S[j][0] + S[j][1];
            rs1 += S[j][2] + S[j][3];
        }
        rs0 += __shfl_xor_sync(0xffffffffu, rs0, 1);
        rs0 += __shfl_xor_sync(0xffffffffu, rs0, 2);
        rs1 += __shfl_xor_sync(0xffffffffu, rs1, 1);
        rs1 += __shfl_xor_sync(0xffffffffu, rs1, 2);
        l0 += rs0; l1 += rs1;
        m0 = mn0; m1 = mn1;

        // ---- O += P @ V (3-term split, term-major issue) ----
#pragma unroll
        for (int s = 0; s < 4; s++) {
            uint32_t pah[4], pal[4];
#pragma unroll
            for (int half = 0; half < 2; half++) {
                const float* Sf = S[2 * s + half];
                __nv_bfloat162 hp0 = __floats2bfloat162_rn(Sf[0], Sf[1]);
                float2 hf0 = __bfloat1622float2(hp0);
                __nv_bfloat162 lp0 = __floats2bfloat162_rn(Sf[0] - hf0.x, Sf[1] - hf0.y);
                __nv_bfloat162 hp1 = __floats2bfloat162_rn(Sf[2], Sf[3]);
                float2 hf1 = __bfloat1622float2(hp1);
                __nv_bfloat162 lp1 = __floats2bfloat162_rn(Sf[2] - hf1.x, Sf[3] - hf1.y);
                pah[2 * half]     = *(uint32_t*)&hp0;
                pah[2 * half + 1] = *(uint32_t*)&hp1;
                pal[2 * half]     = *(uint32_t*)&lp0;
                pal[2 * half + 1] = *(uint32_t*)&lp1;
            }
            uint32_t vh4[4][4], vl4[4][4];
#pragma unroll
            for (int g = 0; g < 4; g++) {
                uint32_t off = SMEM_SWZ((s * 16 + vrow) * 128 + g * 32 + vco);
                ldsm4t(vh4[g], so + AV_H + off);
                ldsm4t(vl4[g], so + AV_L + off);
            }
#pragma unroll
            for (int g = 0; g < 4; g++) {
                mma16816(oa[2 * g],     pah, vh4[g]);
                mma16816(oa[2 * g + 1], pah, vh4[g] + 2);
            }
#pragma unroll
            for (int g = 0; g < 4; g++) {
                mma16816(oa[2 * g],     pah, vl4[g]);
                mma16816(oa[2 * g + 1], pah, vl4[g] + 2);
            }
#pragma unroll
            for (int g = 0; g < 4; g++) {
                mma16816(oa[2 * g],     pal, vh4[g]);
                mma16816(oa[2 * g + 1], pal, vh4[g] + 2);
            }
        }
    }

    // ---- epilogue: normalize, split, write row-major [M][D] ----
    float il0 = 1.f / l0, il1 = 1.f / l1;
    int qrow = q0 + wid * 16 + (lane >> 2);
    size_t base0 = ((size_t)b * S_ + qrow) * D_ + h * DH_ + 2 * (lane & 3);
    size_t base1 = base0 + (size_t)8 * D_;
#pragma unroll
    for (int nf = 0; nf < 8; nf++) {
        float e0 = oa[nf][0] * il0, e1 = oa[nf][1] * il0;
        float e2 = oa[nf][2] * il1, e3 = oa[nf][3] * il1;
        __nv_bfloat162 hp0 = __floats2bfloat162_rn(e0, e1);
        float2 hf0 = __bfloat1622float2(hp0);
        __nv_bfloat162 lp0 = __floats2bfloat162_rn(e0 - hf0.x, e1 - hf0.y);
        __nv_bfloat162 hp1 = __floats2bfloat162_rn(e2, e3);
        float2 hf1 = __bfloat1622float2(hp1);
        __nv_bfloat162 lp1 = __floats2bfloat162_rn(e2 - hf1.x, e3 - hf1.y);
        *(__nv_bfloat162*)(Oh_ + base0 + 8 * nf) = hp0;
        *(__nv_bfloat162*)(Ol_ + base0 + 8 * nf) = lp0;
        *(__nv_bfloat162*)(Oh_ + base1 + 8 * nf) = hp1;
        *(__nv_bfloat162*)(Ol_ + base1 + 8 * nf) = lp1;
    }
}

// ---------------------------------------------------------------------------
// fp32 -> split bf16 (row-major, for input v)
// ---------------------------------------------------------------------------
__global__ __launch_bounds__(256) void split_bf16_kernel(
    const float4* __restrict__ x, __nv_bfloat162* __restrict__ hi,
    __nv_bfloat162* __restrict__ lo, int n4)
{
    int i = blockIdx.x * blockDim.x + threadIdx.x;
    if (i >= n4) return;
    float4 v = x[i];
    __nv_bfloat162 a = __floats2bfloat162_rn(v.x, v.y);
    __nv_bfloat162 b = __floats2bfloat162_rn(v.z, v.w);
    float2 fa = __bfloat1622float2(a), fb = __bfloat1622float2(b);
    __nv_bfloat162 c = __floats2bfloat162_rn(v.x - fa.x, v.y - fa.y);
    __nv_bfloat162 d = __floats2bfloat162_rn(v.z - fb.x, v.w - fb.y);
    hi[2 * i] = a; hi[2 * i + 1] = b;
    lo[2 * i] = c; lo[2 * i + 1] = d;
}

// ---------------------------------------------------------------------------
// W[K,N] fp32 -> W^T[N,K] split bf16   grid (32,32), block (32,8)
// ---------------------------------------------------------------------------
__global__ __launch_bounds__(256) void transpose_split(
    const float* __restrict__ W, __nv_bfloat16* __restrict__ Th,
    __nv_bfloat16* __restrict__ Tl)
{
    __shared__ float t[32][33];
    const int n0 = blockIdx.x * 32, k0 = blockIdx.y * 32;
    const int tx = threadIdx.x, ty = threadIdx.y;
#pragma unroll
    for (int i = 0; i < 4; i++)
        t[ty + i * 8][tx] = W[(size_t)(k0 + ty + i * 8) * D_ + n0 + tx];
    __syncthreads();
#pragma unroll
    for (int i = 0; i < 4; i++) {
        int n = n0 + ty + i * 8;
        float v = t[tx][ty + i * 8];
        __nv_bfloat16 h = __float2bfloat16(v);
        __nv_bfloat16 l = __float2bfloat16(v - __bfloat162float(h));
        Th[(size_t)n * D_ + k0 + tx] = h;
        Tl[(size_t)n * D_ + k0 + tx] = l;
    }
}

// ---------------------------------------------------------------------------
// Launch
// ---------------------------------------------------------------------------
extern "C" void kernel_launch(void* const* d_in, const int* in_sizes, int n_in,
                              void* d_out, int out_size)
{
    (void)in_sizes; (void)n_in; (void)out_size;
    const float* v       = (const float*)d_in[0];
    const int*   lengths = (const int*)  d_in[1];
    const float* Wq      = (const float*)d_in[2];
    const float* bq      = (const float*)d_in[3];
    const float* Wk      = (const float*)d_in[4];
    const float* bk      = (const float*)d_in[5];
    const float* Wv      = (const float*)d_in[6];
    const float* bv      = (const float*)d_in[7];
    const float* Wo      = (const float*)d_in[8];
    const float* bo      = (const float*)d_in[9];
    float* out = (float*)d_out;

    __nv_bfloat16 *ah, *al, *bh, *bl, *qh, *ql, *kh, *kl, *vh, *vl;
    cudaGetSymbolAddress((void**)&ah, g_Ah);
    cudaGetSymbolAddress((void**)&al, g_Al);
    cudaGetSymbolAddress((void**)&bh, g_Bh);
    cudaGetSymbolAddress((void**)&bl, g_Bl);
    cudaGetSymbolAddress((void**)&qh, g_Qh);
    cudaGetSymbolAddress((void**)&ql, g_Ql);
    cudaGetSymbolAddress((void**)&kh, g_Kh);
    cudaGetSymbolAddress((void**)&kl, g_Kl);
    cudaGetSymbolAddress((void**)&vh, g_Vh);
    cudaGetSymbolAddress((void**)&vl, g_Vl);

    cudaFuncSetAttribute(gemm_mma<0, false>, cudaFuncAttributeMaxDynamicSharedMemorySize, GEMM_SMEM);
    cudaFuncSetAttribute(gemm_mma<1, false>, cudaFuncAttributeMaxDynamicSharedMemorySize, GEMM_SMEM);
    cudaFuncSetAttribute(gemm_mma<1, true>,  cudaFuncAttributeMaxDynamicSharedMemorySize, GEMM_SMEM);
    cudaFuncSetAttribute(attn_mma, cudaFuncAttributeMaxDynamicSharedMemorySize, ATTN_SMEM);

    const int n4 = M_ * D_ / 4;
    dim3 gsplit((n4 + 255) / 256);
    dim3 gtr(32, 32), btr(32, 8);
    dim3 gg(D_ / 128, M_ / 128);   // (8, 64)

    split_bf16_kernel<<<gsplit, 256>>>((const float4*)v,
        (__nv_bfloat162*)ah, (__nv_bfloat162*)al, n4);

    transpose_split<<<gtr, btr>>>(Wq, bh, bl);
    gemm_mma<1, false><<<gg, 256, GEMM_SMEM>>>(ah, al, bh, bl, bq, nullptr, qh, ql, nullptr);
    transpose_split<<<gtr, btr>>>(Wk, bh, bl);
    gemm_mma<1, true><<<gg, 256, GEMM_SMEM>>>(ah, al, bh, bl, bk, nullptr, kh, kl, lengths);
    transpose_split<<<gtr, btr>>>(Wv, bh, bl);
    gemm_mma<1, true><<<gg, 256, GEMM_SMEM>>>(ah, al, bh, bl, bv, nullptr, vh, vl, lengths);

    dim3 ga(S_ / 128, H_, B_);     // (4, 16, 16)
    attn_mma<<<ga, 256, ATTN_SMEM>>>(qh, ql, kh, kl, vh, vl, lengths, ah, al);

    transpose_split<<<gtr, btr>>>(Wo, bh, bl);
    gemm_mma<0, false><<<gg, 256, GEMM_SMEM>>>(ah, al, bh, bl, bo, out, nullptr, nullptr, nullptr);
}

// round 9
// speedup vs baseline: 1.1210x; 1.1210x over previous
#include <cuda_runtime.h>
#include <cuda_bf16.h>
#include <cstdint>
#include <cstddef>

// Problem constants
#define B_  16
#define S_  512
#define D_  1024
#define H_  16
#define DH_ 64
#define M_  (B_ * S_)   // 8192

// ---------------------------------------------------------------------------
// Scratch (static device globals)
// ---------------------------------------------------------------------------
__device__ __align__(128) __nv_bfloat16 g_Ah[M_ * D_];   // v-split, later attn out (row-major)
__device__ __align__(128) __nv_bfloat16 g_Al[M_ * D_];
__device__ __align__(128) __nv_bfloat16 g_Bh[4 * D_ * D_]; // concat W^T hi [4096][1024] (Q,K,V,O)
__device__ __align__(128) __nv_bfloat16 g_Bl[4 * D_ * D_]; // concat W^T lo
__device__ __align__(128) __nv_bfloat16 g_Qh[M_ * D_];   // head-major [b,h,s,dh]
__device__ __align__(128) __nv_bfloat16 g_Ql[M_ * D_];
__device__ __align__(128) __nv_bfloat16 g_Kh[M_ * D_];
__device__ __align__(128) __nv_bfloat16 g_Kl[M_ * D_];
__device__ __align__(128) __nv_bfloat16 g_Vh[M_ * D_];
__device__ __align__(128) __nv_bfloat16 g_Vl[M_ * D_];

// ---------------------------------------------------------------------------
// PTX helpers (sm_80+ features only; compute_103 lowering rejects sm_103a-only)
// ---------------------------------------------------------------------------
__device__ __forceinline__ uint32_t smem_u32(const void* p) {
    uint32_t a;
    asm("{ .reg .u64 t; cvta.to.shared.u64 t, %1; cvt.u32.u64 %0, t; }" : "=r"(a) : "l"(p));
    return a;
}
__device__ __forceinline__ void cp16(uint32_t saddr, const void* gaddr) {
    asm volatile("cp.async.cg.shared.global [%0], [%1], 16;" :: "r"(saddr), "l"(gaddr) : "memory");
}
#define CP_COMMIT() asm volatile("cp.async.commit_group;" ::: "memory")
#define CP_WAIT0()  asm volatile("cp.async.wait_group 0;" ::: "memory")
#define CP_WAIT1()  asm volatile("cp.async.wait_group 1;" ::: "memory")
#define CP_WAIT2()  asm volatile("cp.async.wait_group 2;" ::: "memory")

__device__ __forceinline__ void ldsm4(uint32_t* r, uint32_t a) {
    asm volatile("ldmatrix.sync.aligned.m8n8.x4.shared.b16 {%0,%1,%2,%3}, [%4];"
                 : "=r"(r[0]), "=r"(r[1]), "=r"(r[2]), "=r"(r[3]) : "r"(a));
}
__device__ __forceinline__ void ldsm4t(uint32_t* r, uint32_t a) {
    asm volatile("ldmatrix.sync.aligned.m8n8.x4.trans.shared.b16 {%0,%1,%2,%3}, [%4];"
                 : "=r"(r[0]), "=r"(r[1]), "=r"(r[2]), "=r"(r[3]) : "r"(a));
}
__device__ __forceinline__ void mma16816(float* c, const uint32_t* a, const uint32_t* b) {
    asm volatile(
        "mma.sync.aligned.m16n8k16.row.col.f32.bf16.bf16.f32 "
        "{%0,%1,%2,%3}, {%4,%5,%6,%7}, {%8,%9}, {%0,%1,%2,%3};"
        : "+f"(c[0]), "+f"(c[1]), "+f"(c[2]), "+f"(c[3])
        : "r"(a[0]), "r"(a[1]), "r"(a[2]), "r"(a[3]), "r"(b[0]), "r"(b[1]));
}

#define SMEM_SWZ(o) ((o) ^ (((o) >> 3) & 0x70))

// ---------------------------------------------------------------------------
// Shared GEMM plumbing: CTA tile 128x128, BK=64, 3-stage cp.async, 8 warps 2x4.
// ---------------------------------------------------------------------------
#define T_AH 0
#define T_AL 16384
#define T_BH 32768
#define T_BL 49152
#define STAGE_BYTES 65536
#define GEMM_SMEM (3 * STAGE_BYTES)   // 196608

__device__ __forceinline__ void load_tile16(uint32_t sdst, const __nv_bfloat16* g,
                                            int row0, int kc, int tid) {
#pragma unroll
    for (int i = 0; i < 4; i++) {
        int idx = tid + i * 256;
        int r = idx >> 3, c = idx & 7;
        const __nv_bfloat16* gp = g + (size_t)(row0 + r) * D_ + kc * 64 + c * 8;
        cp16(sdst + SMEM_SWZ(r * 128 + c * 16), gp);
    }
}

// Mainloop: fills acc[4][4][4] for this warp. Bc points to concat-W row n0.
__device__ __forceinline__ void gemm_mainloop(
    uint32_t sb, const __nv_bfloat16* Ah, const __nv_bfloat16* Al,
    const __nv_bfloat16* Bhp, const __nv_bfloat16* Blp,
    int m0, int tid, int wid, int lane, float acc[4][4][4])
{
    const int wm = (wid >> 2) * 64;
    const int wn = (wid & 3) * 32;
    const int a_row = wm + (lane & 15);
    const int a_coff = (lane >> 4) * 16;
    const int b_row = wn + ((lane >> 4) << 3) + (lane & 7);
    const int b_coff = ((lane >> 3) & 1) * 16;

#pragma unroll
    for (int p = 0; p < 2; p++) {
        uint32_t so = sb + p * STAGE_BYTES;
        load_tile16(so + T_AH, Ah, m0, p, tid);
        load_tile16(so + T_AL, Al, m0, p, tid);
        load_tile16(so + T_BH, Bhp, 0, p, tid);
        load_tile16(so + T_BL, Blp, 0, p, tid);
        CP_COMMIT();
    }

    int stage = 0, nstage = 2;
#pragma unroll 1
    for (int c = 0; c < 16; c++) {
        if (c + 2 < 16) {
            uint32_t so = sb + nstage * STAGE_BYTES;
            load_tile16(so + T_AH, Ah, m0, c + 2, tid);
            load_tile16(so + T_AL, Al, m0, c + 2, tid);
            load_tile16(so + T_BH, Bhp, 0, c + 2, tid);
            load_tile16(so + T_BL, Blp, 0, c + 2, tid);
            CP_COMMIT();
            CP_WAIT2();
        } else if (c + 1 < 16) {
            CP_WAIT1();
        } else {
            CP_WAIT0();
        }
        __syncthreads();

        const uint32_t so = sb + stage * STAGE_BYTES;
#pragma unroll
        for (int ks = 0; ks < 4; ks++) {
            const int kb = ks * 32;
            uint32_t ah[4][4], al[4][4], bh[2][4], bl[2][4];
#pragma unroll
            for (int mt = 0; mt < 4; mt++) {
                uint32_t off = SMEM_SWZ((a_row + mt * 16) * 128 + kb + a_coff);
                ldsm4(ah[mt], so + T_AH + off);
                ldsm4(al[mt], so + T_AL + off);
            }
#pragma unroll
            for (int nt2 = 0; nt2 < 2; nt2++) {
                uint32_t off = SMEM_SWZ((b_row + nt2 * 16) * 128 + kb + b_coff);
                ldsm4(bh[nt2], so + T_BH + off);
                ldsm4(bl[nt2], so + T_BL + off);
            }
#pragma unroll
            for (int mt = 0; mt < 4; mt++)
#pragma unroll
                for (int nt = 0; nt < 4; nt++)
                    mma16816(acc[mt][nt], ah[mt], &bh[nt >> 1][(nt & 1) * 2]);
#pragma unroll
            for (int mt = 0; mt < 4; mt++)
#pragma unroll
                for (int nt = 0; nt < 4; nt++)
                    mma16816(acc[mt][nt], ah[mt], &bl[nt >> 1][(nt & 1) * 2]);
#pragma unroll
            for (int mt = 0; mt < 4; mt++)
#pragma unroll
                for (int nt = 0; nt < 4; nt++)
                    mma16816(acc[mt][nt], al[mt], &bh[nt >> 1][(nt & 1) * 2]);
        }
        __syncthreads();
        stage = (stage + 1) == 3 ? 0 : stage + 1;
        nstage = (nstage + 1) == 3 ? 0 : nstage + 1;
    }
}

// ---------------------------------------------------------------------------
// Fused QKV projection GEMM: C[:, 0:3072] = A @ [Wq|Wk|Wv]^T + bias
// grid (24, 64). proj = n0>>10 selects bias + split-bf16 head-major dest.
// K/V CTAs whose rows attention never reads exit early.
// ---------------------------------------------------------------------------
__global__ __launch_bounds__(256) void gemm_qkv(
    const __nv_bfloat16* __restrict__ Ah, const __nv_bfloat16* __restrict__ Al,
    const __nv_bfloat16* __restrict__ Bh, const __nv_bfloat16* __restrict__ Bl,
    const float* __restrict__ bq, const float* __restrict__ bk, const float* __restrict__ bv,
    __nv_bfloat16* __restrict__ qh, __nv_bfloat16* __restrict__ ql,
    __nv_bfloat16* __restrict__ kh, __nv_bfloat16* __restrict__ kl,
    __nv_bfloat16* __restrict__ vh, __nv_bfloat16* __restrict__ vl,
    const int* __restrict__ lengths)
{
    extern __shared__ __align__(1024) char smem[];
    const int tid  = threadIdx.x;
    const int wid  = tid >> 5, lane = tid & 31;
    const int m0   = blockIdx.y * 128;
    const int n0   = blockIdx.x * 128;     // concat col 0..3071
    const int proj = n0 >> 10;             // 0=Q 1=K 2=V

    if (proj != 0) {
        // attention reads K/V rows [0, ceil(len/64)*64) per batch
        int len = lengths[m0 >> 9];
        if ((m0 & 511) >= ((len + 63) & ~63)) return;
    }

    const float* bias = (proj == 0) ? bq : (proj == 1) ? bk : bv;
    __nv_bfloat16* Ch = (proj == 0) ? qh : (proj == 1) ? kh : vh;
    __nv_bfloat16* Cl = (proj == 0) ? ql : (proj == 1) ? kl : vl;

    uint32_t sb = smem_u32(smem);
    float acc[4][4][4];
#pragma unroll
    for (int i = 0; i < 4; i++)
#pragma unroll
        for (int j = 0; j < 4; j++)
#pragma unroll
            for (int k = 0; k < 4; k++) acc[i][j][k] = 0.f;

    gemm_mainloop(sb, Ah, Al, Bh + (size_t)n0 * D_, Bl + (size_t)n0 * D_,
                  m0, tid, wid, lane, acc);

    const int wm = (wid >> 2) * 64;
    const int wn = (wid & 3) * 32;
    const int er = lane >> 2;
    const int ec = (lane & 3) * 2;
#pragma unroll
    for (int mt = 0; mt < 4; mt++) {
#pragma unroll
        for (int nt = 0; nt < 4; nt++) {
            int row = m0 + wm + mt * 16 + er;
            int lc  = (n0 & 1023) + wn + nt * 8 + ec;   // col within projection
            float b0 = bias[lc], b1 = bias[lc + 1];
            float o0 = acc[mt][nt][0] + b0, o1 = acc[mt][nt][1] + b1;
            float o2 = acc[mt][nt][2] + b0, o3 = acc[mt][nt][3] + b1;
            int bb = row >> 9, ss = row & 511, hh = lc >> 6, dd = lc & 63;
            size_t base = (((size_t)bb * H_ + hh) * S_ + ss) * DH_ + dd;
            __nv_bfloat162 hp = __floats2bfloat162_rn(o0, o1);
            float2 hf = __bfloat1622float2(hp);
            __nv_bfloat162 lp = __floats2bfloat162_rn(o0 - hf.x, o1 - hf.y);
            *(__nv_bfloat162*)(Ch + base) = hp;
            *(__nv_bfloat162*)(Cl + base) = lp;
            __nv_bfloat162 hp2 = __floats2bfloat162_rn(o2, o3);
            float2 hf2 = __bfloat1622float2(hp2);
            __nv_bfloat162 lp2 = __floats2bfloat162_rn(o2 - hf2.x, o3 - hf2.y);
            *(__nv_bfloat162*)(Ch + base + 8 * DH_) = hp2;
            *(__nv_bfloat162*)(Cl + base + 8 * DH_) = lp2;
        }
    }
}

// ---------------------------------------------------------------------------
// Output projection GEMM: out = A @ Wo^T + bo (fp32 row-major), grid (8, 64)
// ---------------------------------------------------------------------------
__global__ __launch_bounds__(256) void gemm_out(
    const __nv_bfloat16* __restrict__ Ah, const __nv_bfloat16* __restrict__ Al,
    const __nv_bfloat16* __restrict__ Bh, const __nv_bfloat16* __restrict__ Bl,
    const float* __restrict__ bias, float* __restrict__ C)
{
    extern __shared__ __align__(1024) char smem[];
    const int tid  = threadIdx.x;
    const int wid  = tid >> 5, lane = tid & 31;
    const int m0   = blockIdx.y * 128;
    const int n0   = blockIdx.x * 128;

    uint32_t sb = smem_u32(smem);
    float acc[4][4][4];
#pragma unroll
    for (int i = 0; i < 4; i++)
#pragma unroll
        for (int j = 0; j < 4; j++)
#pragma unroll
            for (int k = 0; k < 4; k++) acc[i][j][k] = 0.f;

    gemm_mainloop(sb, Ah, Al, Bh + (size_t)n0 * D_, Bl + (size_t)n0 * D_,
                  m0, tid, wid, lane, acc);

    const int wm = (wid >> 2) * 64;
    const int wn = (wid & 3) * 32;
    const int er = lane >> 2;
    const int ec = (lane & 3) * 2;
#pragma unroll
    for (int mt = 0; mt < 4; mt++) {
#pragma unroll
        for (int nt = 0; nt < 4; nt++) {
            int row = m0 + wm + mt * 16 + er;
            int col = n0 + wn + nt * 8 + ec;
            float b0 = bias[col], b1 = bias[col + 1];
            float2 p0 = make_float2(acc[mt][nt][0] + b0, acc[mt][nt][1] + b1);
            float2 p1 = make_float2(acc[mt][nt][2] + b0, acc[mt][nt][3] + b1);
            *(float2*)(C + (size_t)row * D_ + col) = p0;
            *(float2*)(C + (size_t)(row + 8) * D_ + col) = p1;
        }
    }
}

// ---------------------------------------------------------------------------
// HMMA flash attention (unchanged from R7/R8).
// ---------------------------------------------------------------------------
#define AQ_H 0
#define AQ_L 16384
#define AST  32768
#define AK_H 0
#define AK_L 8192
#define AV_H 16384
#define AV_L 24576
#define AST_BYTES 32768
#define ATTN_SMEM (32768 + 2 * AST_BYTES)   // 98304

__global__ __launch_bounds__(256) void attn_mma(
    const __nv_bfloat16* __restrict__ Qh_, const __nv_bfloat16* __restrict__ Ql_,
    const __nv_bfloat16* __restrict__ Kh_, const __nv_bfloat16* __restrict__ Kl_,
    const __nv_bfloat16* __restrict__ Vh_, const __nv_bfloat16* __restrict__ Vl_,
    const int* __restrict__ lengths,
    __nv_bfloat16* __restrict__ Oh_, __nv_bfloat16* __restrict__ Ol_)
{
    extern __shared__ __align__(1024) char smem[];
    const int tid = threadIdx.x, wid = tid >> 5, lane = tid & 31;
    const int b = blockIdx.z, h = blockIdx.y, q0 = blockIdx.x * 128;
    const int len = lengths[b];
    uint32_t sb = smem_u32(smem);
    const size_t bh_off = ((size_t)b * H_ + h) * (S_ * DH_);

#pragma unroll
    for (int i = 0; i < 4; i++) {
        int idx = tid + i * 256;
        int r = idx >> 3, c = idx & 7;
        cp16(sb + AQ_H + SMEM_SWZ(r * 128 + c * 16), Qh_ + bh_off + (size_t)(q0 + r) * DH_ + c * 8);
        cp16(sb + AQ_L + SMEM_SWZ(r * 128 + c * 16), Ql_ + bh_off + (size_t)(q0 + r) * DH_ + c * 8);
    }
    CP_COMMIT();

    const int jend = (len + 63) & ~63;
    const int ntile = jend >> 6;

    {
        uint32_t so = sb + AST;
#pragma unroll
        for (int i = 0; i < 2; i++) {
            int idx = tid + i * 256;
            int r = idx >> 3, c = idx & 7;
            size_t g = bh_off + (size_t)r * DH_ + c * 8;
            uint32_t sw = SMEM_SWZ(r * 128 + c * 16);
            cp16(so + AK_H + sw, Kh_ + g);
            cp16(so + AK_L + sw, Kl_ + g);
            cp16(so + AV_H + sw, Vh_ + g);
            cp16(so + AV_L + sw, Vl_ + g);
        }
        CP_COMMIT();
    }

    CP_WAIT1();
    __syncthreads();

    const int a_row = wid * 16 + (lane & 15);
    const int a_co = (lane >> 4) * 16;
    uint32_t qh[4][4], ql[4][4];
#pragma unroll
    for (int s = 0; s < 4; s++) {
        uint32_t off = SMEM_SWZ(a_row * 128 + s * 32 + a_co);
        ldsm4(qh[s], sb + AQ_H + off);
        ldsm4(ql[s], sb + AQ_L + off);
    }

    float oa[8][4];
#pragma unroll
    for (int i = 0; i < 8; i++)
#pragma unroll
        for (int j = 0; j < 4; j++) oa[i][j] = 0.f;
    float m0 = -1e30f, m1 = -1e30f, l0 = 0.f, l1 = 0.f;

    const int krow = ((lane >> 4) << 3) + (lane & 7);
    const int kco  = ((lane >> 3) & 1) * 16;
    const int vrow = lane & 15;
    const int vco  = (lane >> 4) * 16;

#pragma unroll 1
    for (int t = 0; t < ntile; t++) {
        CP_WAIT0();
        __syncthreads();
        if (t + 1 < ntile) {
            uint32_t so = sb + AST + ((t + 1) & 1) * AST_BYTES;
            int j0n = (t + 1) * 64;
#pragma unroll
            for (int i = 0; i < 2; i++) {
                int idx = tid + i * 256;
                int r = idx >> 3, c = idx & 7;
                size_t g = bh_off + (size_t)(j0n + r) * DH_ + c * 8;
                uint32_t sw = SMEM_SWZ(r * 128 + c * 16);
                cp16(so + AK_H + sw, Kh_ + g);
                cp16(so + AK_L + sw, Kl_ + g);
                cp16(so + AV_H + sw, Vh_ + g);
                cp16(so + AV_L + sw, Vl_ + g);
            }
            CP_COMMIT();
        }

        const uint32_t so = sb + AST + (t & 1) * AST_BYTES;
        const int j0 = t * 64;

        float S[8][4];
#pragma unroll
        for (int i = 0; i < 8; i++)
#pragma unroll
            for (int j = 0; j < 4; j++) S[i][j] = 0.f;
#pragma unroll
        for (int s = 0; s < 4; s++) {
            uint32_t kh4[4][4], kl4[4][4];
#pragma unroll
            for (int g = 0; g < 4; g++) {
                uint32_t off = SMEM_SWZ((g * 16 + krow) * 128 + s * 32 + kco);
                ldsm4(kh4[g], so + AK_H + off);
                ldsm4(kl4[g], so + AK_L + off);
            }
#pragma unroll
            for (int g = 0; g < 4; g++) {
                mma16816(S[2 * g],     qh[s], kh4[g]);
                mma16816(S[2 * g + 1], qh[s], kh4[g] + 2);
            }
#pragma unroll
            for (int g = 0; g < 4; g++) {
                mma16816(S[2 * g],     qh[s], kl4[g]);
                mma16816(S[2 * g + 1], qh[s], kl4[g] + 2);
            }
#pragma unroll
            for (int g = 0; g < 4; g++) {
                mma16816(S[2 * g],     ql[s], kh4[g]);
                mma16816(S[2 * g + 1], ql[s], kh4[g] + 2);
            }
        }

        if (j0 + 64 > len) {
            int kb0 = j0 + 2 * (lane & 3);
#pragma unroll
            for (int j = 0; j < 8; j++) {
#pragma unroll
                for (int e = 0; e < 4; e++) {
                    int kk = kb0 + 8 * j + (e & 1);
                    S[j][e] = (kk < len) ? S[j][e] * 0.125f : -1e9f;
                }
            }
        } else {
#pragma unroll
            for (int j = 0; j < 8; j++)
#pragma unroll
                for (int e = 0; e < 4; e++) S[j][e] *= 0.125f;
        }

        float mx0 = -1e30f, mx1 = -1e30f;
#pragma unroll
        for (int j = 0; j < 8; j++) {
            mx0 = fmaxf(mx0, fmaxf(S[j][0], S[j][1]));
            mx1 = fmaxf(mx1, fmaxf(S[j][2], S[j][3]));
        }
        mx0 = fmaxf(mx0, __shfl_xor_sync(0xffffffffu, mx0, 1));
        mx0 = fmaxf(mx0, __shfl_xor_sync(0xffffffffu, mx0, 2));
        mx1 = fmaxf(mx1, __shfl_xor_sync(0xffffffffu, mx1, 1));
        mx1 = fmaxf(mx1, __shfl_xor_sync(0xffffffffu, mx1, 2));
        float mn0 = fmaxf(m0, mx0), mn1 = fmaxf(m1, mx1);
        float f0 = __expf(m0 - mn0), f1 = __expf(m1 - mn1);
        l0 *= f0; l1 *= f1;
#pragma unroll
        for (int i = 0; i < 8; i++) {
            oa[i][0] *= f0; oa[i][1] *= f0; oa[i][2] *= f1; oa[i][3] *= f1;
        }
        float rs0 = 0.f, rs1 = 0.f;
#pragma unroll
        for (int j = 0; j < 8; j++) {
            S[j][0] = __expf(S[j][0] - mn0);
            S[j][1] = __expf(S[j][1] - mn0);
            S[j][2] = __expf(S[j][2] - mn1);
            S[j][3] = __expf(S[j][3] - mn1);
            rs0 += S[j][0] + S[j][1];
            rs1 += S[j][2] + S[j][3];
        }
        rs0 += __shfl_xor_sync(0xffffffffu, rs0, 1);
        rs0 += __shfl_xor_sync(0xffffffffu, rs0, 2);
        rs1 += __shfl_xor_sync(0xffffffffu, rs1, 1);
        rs1 += __shfl_xor_sync(0xffffffffu, rs1, 2);
        l0 += rs0; l1 += rs1;
        m0 = mn0; m1 = mn1;

#pragma unroll
        for (int s = 0; s < 4; s++) {
            uint32_t pah[4], pal[4];
#pragma unroll
            for (int half = 0; half < 2; half++) {
                const float* Sf = S[2 * s + half];
                __nv_bfloat162 hp0 = __floats2bfloat162_rn(Sf[0], Sf[1]);
                float2 hf0 = __bfloat1622float2(hp0);
                __nv_bfloat162 lp0 = __floats2bfloat162_rn(Sf[0] - hf0.x, Sf[1] - hf0.y);
                __nv_bfloat162 hp1 = __floats2bfloat162_rn(Sf[2], Sf[3]);
                float2 hf1 = __bfloat1622float2(hp1);
                __nv_bfloat162 lp1 = __floats2bfloat162_rn(Sf[2] - hf1.x, Sf[3] - hf1.y);
                pah[2 * half]     = *(uint32_t*)&hp0;
                pah[2 * half + 1] = *(uint32_t*)&hp1;
                pal[2 * half]     = *(uint32_t*)&lp0;
                pal[2 * half + 1] = *(uint32_t*)&lp1;
            }
            uint32_t vh4[4][4], vl4[4][4];
#pragma unroll
            for (int g = 0; g < 4; g++) {
                uint32_t off = SMEM_SWZ((s * 16 + vrow) * 128 + g * 32 + vco);
                ldsm4t(vh4[g], so + AV_H + off);
                ldsm4t(vl4[g], so + AV_L + off);
            }
#pragma unroll
            for (int g = 0; g < 4; g++) {
                mma16816(oa[2 * g],     pah, vh4[g]);
                mma16816(oa[2 * g + 1], pah, vh4[g] + 2);
            }
#pragma unroll
            for (int g = 0; g < 4; g++) {
                mma16816(oa[2 * g],     pah, vl4[g]);
                mma16816(oa[2 * g + 1], pah, vl4[g] + 2);
            }
#pragma unroll
            for (int g = 0; g < 4; g++) {
                mma16816(oa[2 * g],     pal, vh4[g]);
                mma16816(oa[2 * g + 1], pal, vh4[g] + 2);
            }
        }
    }

    float il0 = 1.f / l0, il1 = 1.f / l1;
    int qrow = q0 + wid * 16 + (lane >> 2);
    size_t base0 = ((size_t)b * S_ + qrow) * D_ + h * DH_ + 2 * (lane & 3);
    size_t base1 = base0 + (size_t)8 * D_;
#pragma unroll
    for (int nf = 0; nf < 8; nf++) {
        float e0 = oa[nf][0] * il0, e1 = oa[nf][1] * il0;
        float e2 = oa[nf][2] * il1, e3 = oa[nf][3] * il1;
        __nv_bfloat162 hp0 = __floats2bfloat162_rn(e0, e1);
        float2 hf0 = __bfloat1622float2(hp0);
        __nv_bfloat162 lp0 = __floats2bfloat162_rn(e0 - hf0.x, e1 - hf0.y);
        __nv_bfloat162 hp1 = __floats2bfloat162_rn(e2, e3);
        float2 hf1 = __bfloat1622float2(hp1);
        __nv_bfloat162 lp1 = __floats2bfloat162_rn(e2 - hf1.x, e3 - hf1.y);
        *(__nv_bfloat162*)(Oh_ + base0 + 8 * nf) = hp0;
        *(__nv_bfloat162*)(Ol_ + base0 + 8 * nf) = lp0;
        *(__nv_bfloat162*)(Oh_ + base1 + 8 * nf) = hp1;
        *(__nv_bfloat162*)(Ol_ + base1 + 8 * nf) = lp1;
    }
}

// ---------------------------------------------------------------------------
// fp32 -> split bf16 (row-major, for input v)
// ---------------------------------------------------------------------------
__global__ __launch_bounds__(256) void split_bf16_kernel(
    const float4* __restrict__ x, __nv_bfloat162* __restrict__ hi,
    __nv_bfloat162* __restrict__ lo, int n4)
{
    int i = blockIdx.x * blockDim.x + threadIdx.x;
    if (i >= n4) return;
    float4 v = x[i];
    __nv_bfloat162 a = __floats2bfloat162_rn(v.x, v.y);
    __nv_bfloat162 b = __floats2bfloat162_rn(v.z, v.w);
    float2 fa = __bfloat1622float2(a), fb = __bfloat1622float2(b);
    __nv_bfloat162 c = __floats2bfloat162_rn(v.x - fa.x, v.y - fa.y);
    __nv_bfloat162 d = __floats2bfloat162_rn(v.z - fb.x, v.w - fb.y);
    hi[2 * i] = a; hi[2 * i + 1] = b;
    lo[2 * i] = c; lo[2 * i + 1] = d;
}

// ---------------------------------------------------------------------------
// All 4 weights: W[K,N] fp32 -> concat W^T[4096][1024] split bf16
// grid (32,32,4), block (32,8). z selects the weight; out rows z*1024 + n.
// ---------------------------------------------------------------------------
__global__ __launch_bounds__(256) void transpose_split4(
    const float* __restrict__ W0, const float* __restrict__ W1,
    const float* __restrict__ W2, const float* __restrict__ W3,
    __nv_bfloat16* __restrict__ Th, __nv_bfloat16* __restrict__ Tl)
{
    __shared__ float t[32][33];
    const int z = blockIdx.z;
    const float* W = (z == 0) ? W0 : (z == 1) ? W1 : (z == 2) ? W2 : W3;
    const int n0 = blockIdx.x * 32, k0 = blockIdx.y * 32;
    const int tx = threadIdx.x, ty = threadIdx.y;
#pragma unroll
    for (int i = 0; i < 4; i++)
        t[ty + i * 8][tx] = W[(size_t)(k0 + ty + i * 8) * D_ + n0 + tx];
    __syncthreads();
#pragma unroll
    for (int i = 0; i < 4; i++) {
        int n = z * D_ + n0 + ty + i * 8;
        float v = t[tx][ty + i * 8];
        __nv_bfloat16 h = __float2bfloat16(v);
        __nv_bfloat16 l = __float2bfloat16(v - __bfloat162float(h));
        Th[(size_t)n * D_ + k0 + tx] = h;
        Tl[(size_t)n * D_ + k0 + tx] = l;
    }
}

// ---------------------------------------------------------------------------
// Launch
// ---------------------------------------------------------------------------
extern "C" void kernel_launch(void* const* d_in, const int* in_sizes, int n_in,
                              void* d_out, int out_size)
{
    (void)in_sizes; (void)n_in; (void)out_size;
    const float* v       = (const float*)d_in[0];
    const int*   lengths = (const int*)  d_in[1];
    const float* Wq      = (const float*)d_in[2];
    const float* bq      = (const float*)d_in[3];
    const float* Wk      = (const float*)d_in[4];
    const float* bk      = (const float*)d_in[5];
    const float* Wv      = (const float*)d_in[6];
    const float* bv      = (const float*)d_in[7];
    const float* Wo      = (const float*)d_in[8];
    const float* bo      = (const float*)d_in[9];
    float* out = (float*)d_out;

    __nv_bfloat16 *ah, *al, *bh, *bl, *qh, *ql, *kh, *kl, *vh, *vl;
    cudaGetSymbolAddress((void**)&ah, g_Ah);
    cudaGetSymbolAddress((void**)&al, g_Al);
    cudaGetSymbolAddress((void**)&bh, g_Bh);
    cudaGetSymbolAddress((void**)&bl, g_Bl);
    cudaGetSymbolAddress((void**)&qh, g_Qh);
    cudaGetSymbolAddress((void**)&ql, g_Ql);
    cudaGetSymbolAddress((void**)&kh, g_Kh);
    cudaGetSymbolAddress((void**)&kl, g_Kl);
    cudaGetSymbolAddress((void**)&vh, g_Vh);
    cudaGetSymbolAddress((void**)&vl, g_Vl);

    cudaFuncSetAttribute(gemm_qkv, cudaFuncAttributeMaxDynamicSharedMemorySize, GEMM_SMEM);
    cudaFuncSetAttribute(gemm_out, cudaFuncAttributeMaxDynamicSharedMemorySize, GEMM_SMEM);
    cudaFuncSetAttribute(attn_mma, cudaFuncAttributeMaxDynamicSharedMemorySize, ATTN_SMEM);

    const int n4 = M_ * D_ / 4;
    dim3 gsplit((n4 + 255) / 256);
    dim3 gtr(32, 32, 4), btr(32, 8);

    transpose_split4<<<gtr, btr>>>(Wq, Wk, Wv, Wo, bh, bl);
    split_bf16_kernel<<<gsplit, 256>>>((const float4*)v,
        (__nv_bfloat162*)ah, (__nv_bfloat162*)al, n4);

    dim3 gqkv(3 * D_ / 128, M_ / 128);   // (24, 64)
    gemm_qkv<<<gqkv, 256, GEMM_SMEM>>>(ah, al, bh, bl, bq, bk, bv,
                                       qh, ql, kh, kl, vh, vl, lengths);

    dim3 ga(S_ / 128, H_, B_);           // (4, 16, 16)
    attn_mma<<<ga, 256, ATTN_SMEM>>>(qh, ql, kh, kl, vh, vl, lengths, ah, al);

    dim3 go(D_ / 128, M_ / 128);         // (8, 64)
    gemm_out<<<go, 256, GEMM_SMEM>>>(ah, al,
                                     bh + (size_t)3 * D_ * D_,
                                     bl + (size_t)3 * D_ * D_, bo, out);
}

// round 10
// speedup vs baseline: 1.1333x; 1.0110x over previous
#include <cuda_runtime.h>
#include <cuda_bf16.h>
#include <cstdint>
#include <cstddef>

// Problem constants
#define B_  16
#define S_  512
#define D_  1024
#define H_  16
#define DH_ 64
#define M_  (B_ * S_)   // 8192

// ---------------------------------------------------------------------------
// Scratch (static device globals)
// ---------------------------------------------------------------------------
__device__ __align__(128) __nv_bfloat16 g_Ah[M_ * D_];   // v-split, later attn out (row-major)
__device__ __align__(128) __nv_bfloat16 g_Al[M_ * D_];
__device__ __align__(128) __nv_bfloat16 g_Bh[4 * D_ * D_]; // concat W^T hi [4096][1024] (Q,K,V,O)
__device__ __align__(128) __nv_bfloat16 g_Bl[4 * D_ * D_]; // concat W^T lo
__device__ __align__(128) __nv_bfloat16 g_Qh[M_ * D_];   // head-major [b,h,s,dh]
__device__ __align__(128) __nv_bfloat16 g_Ql[M_ * D_];
__device__ __align__(128) __nv_bfloat16 g_Kh[M_ * D_];
__device__ __align__(128) __nv_bfloat16 g_Kl[M_ * D_];
__device__ __align__(128) __nv_bfloat16 g_Vh[M_ * D_];
__device__ __align__(128) __nv_bfloat16 g_Vl[M_ * D_];

// ---------------------------------------------------------------------------
// PTX helpers (sm_80+ features only; compute_103 lowering rejects sm_103a-only)
// ---------------------------------------------------------------------------
__device__ __forceinline__ uint32_t smem_u32(const void* p) {
    uint32_t a;
    asm("{ .reg .u64 t; cvta.to.shared.u64 t, %1; cvt.u32.u64 %0, t; }" : "=r"(a) : "l"(p));
    return a;
}
__device__ __forceinline__ void cp16(uint32_t saddr, const void* gaddr) {
    asm volatile("cp.async.cg.shared.global [%0], [%1], 16;" :: "r"(saddr), "l"(gaddr) : "memory");
}
#define CP_COMMIT() asm volatile("cp.async.commit_group;" ::: "memory")
#define CP_WAIT0()  asm volatile("cp.async.wait_group 0;" ::: "memory")
#define CP_WAIT1()  asm volatile("cp.async.wait_group 1;" ::: "memory")
#define CP_WAIT2()  asm volatile("cp.async.wait_group 2;" ::: "memory")

__device__ __forceinline__ void ldsm4(uint32_t* r, uint32_t a) {
    asm volatile("ldmatrix.sync.aligned.m8n8.x4.shared.b16 {%0,%1,%2,%3}, [%4];"
                 : "=r"(r[0]), "=r"(r[1]), "=r"(r[2]), "=r"(r[3]) : "r"(a));
}
__device__ __forceinline__ void ldsm4t(uint32_t* r, uint32_t a) {
    asm volatile("ldmatrix.sync.aligned.m8n8.x4.trans.shared.b16 {%0,%1,%2,%3}, [%4];"
                 : "=r"(r[0]), "=r"(r[1]), "=r"(r[2]), "=r"(r[3]) : "r"(a));
}
__device__ __forceinline__ void mma16816(float* c, const uint32_t* a, const uint32_t* b) {
    asm volatile(
        "mma.sync.aligned.m16n8k16.row.col.f32.bf16.bf16.f32 "
        "{%0,%1,%2,%3}, {%4,%5,%6,%7}, {%8,%9}, {%0,%1,%2,%3};"
        : "+f"(c[0]), "+f"(c[1]), "+f"(c[2]), "+f"(c[3])
        : "r"(a[0]), "r"(a[1]), "r"(a[2]), "r"(a[3]), "r"(b[0]), "r"(b[1]));
}

#define SMEM_SWZ(o)   ((o) ^ (((o) >> 3) & 0x70))   // 128B rows
#define SMEM_SWZ32(o) ((o) ^ (((o) >> 3) & 0x30))   // 64B rows (BK=32)

// ---------------------------------------------------------------------------
// Shared GEMM plumbing: CTA tile 128x128, BK=32, 3-stage cp.async, 8 warps 2x4,
// 2 CTAs/SM (96KB smem, <=128 regs).
// ---------------------------------------------------------------------------
#define T_AH 0
#define T_AL 8192
#define T_BH 16384
#define T_BL 24576
#define STAGE_BYTES 32768
#define GEMM_SMEM (3 * STAGE_BYTES)   // 98304

__device__ __forceinline__ void load_tile32(uint32_t sdst, const __nv_bfloat16* g,
                                            int row0, int kc, int tid) {
#pragma unroll
    for (int i = 0; i < 2; i++) {
        int idx = tid + i * 256;          // 512 transfers of 16B
        int r = idx >> 2, c = idx & 3;    // 128 rows x 4 chunks
        const __nv_bfloat16* gp = g + (size_t)(row0 + r) * D_ + kc * 32 + c * 8;
        cp16(sdst + SMEM_SWZ32(r * 64 + c * 16), gp);
    }
}

__device__ __forceinline__ void gemm_mainloop(
    uint32_t sb, const __nv_bfloat16* Ah, const __nv_bfloat16* Al,
    const __nv_bfloat16* Bhp, const __nv_bfloat16* Blp,
    int m0, int tid, int wid, int lane, float acc[4][4][4])
{
    const int wm = (wid >> 2) * 64;
    const int wn = (wid & 3) * 32;
    const int a_row = wm + (lane & 15);
    const int a_coff = (lane >> 4) * 16;
    const int b_row = wn + ((lane >> 4) << 3) + (lane & 7);
    const int b_coff = ((lane >> 3) & 1) * 16;

#pragma unroll
    for (int p = 0; p < 2; p++) {
        uint32_t so = sb + p * STAGE_BYTES;
        load_tile32(so + T_AH, Ah, m0, p, tid);
        load_tile32(so + T_AL, Al, m0, p, tid);
        load_tile32(so + T_BH, Bhp, 0, p, tid);
        load_tile32(so + T_BL, Blp, 0, p, tid);
        CP_COMMIT();
    }

    int stage = 0, nstage = 2;
#pragma unroll 1
    for (int c = 0; c < 32; c++) {
        if (c + 2 < 32) {
            uint32_t so = sb + nstage * STAGE_BYTES;
            load_tile32(so + T_AH, Ah, m0, c + 2, tid);
            load_tile32(so + T_AL, Al, m0, c + 2, tid);
            load_tile32(so + T_BH, Bhp, 0, c + 2, tid);
            load_tile32(so + T_BL, Blp, 0, c + 2, tid);
            CP_COMMIT();
            CP_WAIT2();
        } else if (c + 1 < 32) {
            CP_WAIT1();
        } else {
            CP_WAIT0();
        }
        __syncthreads();

        const uint32_t so = sb + stage * STAGE_BYTES;
#pragma unroll
        for (int ks = 0; ks < 2; ks++) {
            const int kb = ks * 32;
            uint32_t ah[4][4], al[4][4], bh[2][4], bl[2][4];
#pragma unroll
            for (int mt = 0; mt < 4; mt++) {
                uint32_t off = SMEM_SWZ32((a_row + mt * 16) * 64 + kb + a_coff);
                ldsm4(ah[mt], so + T_AH + off);
                ldsm4(al[mt], so + T_AL + off);
            }
#pragma unroll
            for (int nt2 = 0; nt2 < 2; nt2++) {
                uint32_t off = SMEM_SWZ32((b_row + nt2 * 16) * 64 + kb + b_coff);
                ldsm4(bh[nt2], so + T_BH + off);
                ldsm4(bl[nt2], so + T_BL + off);
            }
#pragma unroll
            for (int mt = 0; mt < 4; mt++)
#pragma unroll
                for (int nt = 0; nt < 4; nt++)
                    mma16816(acc[mt][nt], ah[mt], &bh[nt >> 1][(nt & 1) * 2]);
#pragma unroll
            for (int mt = 0; mt < 4; mt++)
#pragma unroll
                for (int nt = 0; nt < 4; nt++)
                    mma16816(acc[mt][nt], ah[mt], &bl[nt >> 1][(nt & 1) * 2]);
#pragma unroll
            for (int mt = 0; mt < 4; mt++)
#pragma unroll
                for (int nt = 0; nt < 4; nt++)
                    mma16816(acc[mt][nt], al[mt], &bh[nt >> 1][(nt & 1) * 2]);
        }
        __syncthreads();
        stage = (stage + 1) == 3 ? 0 : stage + 1;
        nstage = (nstage + 1) == 3 ? 0 : nstage + 1;
    }
}

// ---------------------------------------------------------------------------
// Fused QKV projection GEMM: grid (24, 64); proj = n0>>10. K/V skip by length.
// ---------------------------------------------------------------------------
__global__ __launch_bounds__(256, 2) void gemm_qkv(
    const __nv_bfloat16* __restrict__ Ah, const __nv_bfloat16* __restrict__ Al,
    const __nv_bfloat16* __restrict__ Bh, const __nv_bfloat16* __restrict__ Bl,
    const float* __restrict__ bq, const float* __restrict__ bk, const float* __restrict__ bv,
    __nv_bfloat16* __restrict__ qh, __nv_bfloat16* __restrict__ ql,
    __nv_bfloat16* __restrict__ kh, __nv_bfloat16* __restrict__ kl,
    __nv_bfloat16* __restrict__ vh, __nv_bfloat16* __restrict__ vl,
    const int* __restrict__ lengths)
{
    extern __shared__ __align__(1024) char smem[];
    const int tid  = threadIdx.x;
    const int wid  = tid >> 5, lane = tid & 31;
    const int m0   = blockIdx.y * 128;
    const int n0   = blockIdx.x * 128;
    const int proj = n0 >> 10;

    if (proj != 0) {
        int len = lengths[m0 >> 9];
        if ((m0 & 511) >= ((len + 63) & ~63)) return;
    }

    const float* bias = (proj == 0) ? bq : (proj == 1) ? bk : bv;
    __nv_bfloat16* Ch = (proj == 0) ? qh : (proj == 1) ? kh : vh;
    __nv_bfloat16* Cl = (proj == 0) ? ql : (proj == 1) ? kl : vl;

    uint32_t sb = smem_u32(smem);
    float acc[4][4][4];
#pragma unroll
    for (int i = 0; i < 4; i++)
#pragma unroll
        for (int j = 0; j < 4; j++)
#pragma unroll
            for (int k = 0; k < 4; k++) acc[i][j][k] = 0.f;

    gemm_mainloop(sb, Ah, Al, Bh + (size_t)n0 * D_, Bl + (size_t)n0 * D_,
                  m0, tid, wid, lane, acc);

    const int wm = (wid >> 2) * 64;
    const int wn = (wid & 3) * 32;
    const int er = lane >> 2;
    const int ec = (lane & 3) * 2;
#pragma unroll
    for (int mt = 0; mt < 4; mt++) {
#pragma unroll
        for (int nt = 0; nt < 4; nt++) {
            int row = m0 + wm + mt * 16 + er;
            int lc  = (n0 & 1023) + wn + nt * 8 + ec;
            float b0 = bias[lc], b1 = bias[lc + 1];
            float o0 = acc[mt][nt][0] + b0, o1 = acc[mt][nt][1] + b1;
            float o2 = acc[mt][nt][2] + b0, o3 = acc[mt][nt][3] + b1;
            int bb = row >> 9, ss = row & 511, hh = lc >> 6, dd = lc & 63;
            size_t base = (((size_t)bb * H_ + hh) * S_ + ss) * DH_ + dd;
            __nv_bfloat162 hp = __floats2bfloat162_rn(o0, o1);
            float2 hf = __bfloat1622float2(hp);
            __nv_bfloat162 lp = __floats2bfloat162_rn(o0 - hf.x, o1 - hf.y);
            *(__nv_bfloat162*)(Ch + base) = hp;
            *(__nv_bfloat162*)(Cl + base) = lp;
            __nv_bfloat162 hp2 = __floats2bfloat162_rn(o2, o3);
            float2 hf2 = __bfloat1622float2(hp2);
            __nv_bfloat162 lp2 = __floats2bfloat162_rn(o2 - hf2.x, o3 - hf2.y);
            *(__nv_bfloat162*)(Ch + base + 8 * DH_) = hp2;
            *(__nv_bfloat162*)(Cl + base + 8 * DH_) = lp2;
        }
    }
}

// ---------------------------------------------------------------------------
// Output projection GEMM: out = A @ Wo^T + bo (fp32 row-major), grid (8, 64)
// ---------------------------------------------------------------------------
__global__ __launch_bounds__(256, 2) void gemm_out(
    const __nv_bfloat16* __restrict__ Ah, const __nv_bfloat16* __restrict__ Al,
    const __nv_bfloat16* __restrict__ Bh, const __nv_bfloat16* __restrict__ Bl,
    const float* __restrict__ bias, float* __restrict__ C)
{
    extern __shared__ __align__(1024) char smem[];
    const int tid  = threadIdx.x;
    const int wid  = tid >> 5, lane = tid & 31;
    const int m0   = blockIdx.y * 128;
    const int n0   = blockIdx.x * 128;

    uint32_t sb = smem_u32(smem);
    float acc[4][4][4];
#pragma unroll
    for (int i = 0; i < 4; i++)
#pragma unroll
        for (int j = 0; j < 4; j++)
#pragma unroll
            for (int k = 0; k < 4; k++) acc[i][j][k] = 0.f;

    gemm_mainloop(sb, Ah, Al, Bh + (size_t)n0 * D_, Bl + (size_t)n0 * D_,
                  m0, tid, wid, lane, acc);

    const int wm = (wid >> 2) * 64;
    const int wn = (wid & 3) * 32;
    const int er = lane >> 2;
    const int ec = (lane & 3) * 2;
#pragma unroll
    for (int mt = 0; mt < 4; mt++) {
#pragma unroll
        for (int nt = 0; nt < 4; nt++) {
            int row = m0 + wm + mt * 16 + er;
            int col = n0 + wn + nt * 8 + ec;
            float b0 = bias[col], b1 = bias[col + 1];
            float2 p0 = make_float2(acc[mt][nt][0] + b0, acc[mt][nt][1] + b1);
            float2 p1 = make_float2(acc[mt][nt][2] + b0, acc[mt][nt][3] + b1);
            *(float2*)(C + (size_t)row * D_ + col) = p0;
            *(float2*)(C + (size_t)(row + 8) * D_ + col) = p1;
        }
    }
}

// ---------------------------------------------------------------------------
// HMMA flash attention. 2 CTAs/SM: ql fragments reloaded from smem per tile
// (Q stays resident in smem), reg cap 128.
// ---------------------------------------------------------------------------
#define AQ_H 0
#define AQ_L 16384
#define AST  32768
#define AK_H 0
#define AK_L 8192
#define AV_H 16384
#define AV_L 24576
#define AST_BYTES 32768
#define ATTN_SMEM (32768 + 2 * AST_BYTES)   // 98304

__global__ __launch_bounds__(256, 2) void attn_mma(
    const __nv_bfloat16* __restrict__ Qh_, const __nv_bfloat16* __restrict__ Ql_,
    const __nv_bfloat16* __restrict__ Kh_, const __nv_bfloat16* __restrict__ Kl_,
    const __nv_bfloat16* __restrict__ Vh_, const __nv_bfloat16* __restrict__ Vl_,
    const int* __restrict__ lengths,
    __nv_bfloat16* __restrict__ Oh_, __nv_bfloat16* __restrict__ Ol_)
{
    extern __shared__ __align__(1024) char smem[];
    const int tid = threadIdx.x, wid = tid >> 5, lane = tid & 31;
    const int b = blockIdx.z, h = blockIdx.y, q0 = blockIdx.x * 128;
    const int len = lengths[b];
    uint32_t sb = smem_u32(smem);
    const size_t bh_off = ((size_t)b * H_ + h) * (S_ * DH_);

#pragma unroll
    for (int i = 0; i < 4; i++) {
        int idx = tid + i * 256;
        int r = idx >> 3, c = idx & 7;
        cp16(sb + AQ_H + SMEM_SWZ(r * 128 + c * 16), Qh_ + bh_off + (size_t)(q0 + r) * DH_ + c * 8);
        cp16(sb + AQ_L + SMEM_SWZ(r * 128 + c * 16), Ql_ + bh_off + (size_t)(q0 + r) * DH_ + c * 8);
    }
    CP_COMMIT();

    const int jend = (len + 63) & ~63;
    const int ntile = jend >> 6;

    {
        uint32_t so = sb + AST;
#pragma unroll
        for (int i = 0; i < 2; i++) {
            int idx = tid + i * 256;
            int r = idx >> 3, c = idx & 7;
            size_t g = bh_off + (size_t)r * DH_ + c * 8;
            uint32_t sw = SMEM_SWZ(r * 128 + c * 16);
            cp16(so + AK_H + sw, Kh_ + g);
            cp16(so + AK_L + sw, Kl_ + g);
            cp16(so + AV_H + sw, Vh_ + g);
            cp16(so + AV_L + sw, Vl_ + g);
        }
        CP_COMMIT();
    }

    CP_WAIT1();
    __syncthreads();

    const int a_row = wid * 16 + (lane & 15);
    const int a_co = (lane >> 4) * 16;
    uint32_t qh[4][4];                       // hi Q resident; lo reloaded per tile
#pragma unroll
    for (int s = 0; s < 4; s++) {
        uint32_t off = SMEM_SWZ(a_row * 128 + s * 32 + a_co);
        ldsm4(qh[s], sb + AQ_H + off);
    }

    float oa[8][4];
#pragma unroll
    for (int i = 0; i < 8; i++)
#pragma unroll
        for (int j = 0; j < 4; j++) oa[i][j] = 0.f;
    float m0 = -1e30f, m1 = -1e30f, l0 = 0.f, l1 = 0.f;

    const int krow = ((lane >> 4) << 3) + (lane & 7);
    const int kco  = ((lane >> 3) & 1) * 16;
    const int vrow = lane & 15;
    const int vco  = (lane >> 4) * 16;

#pragma unroll 1
    for (int t = 0; t < ntile; t++) {
        CP_WAIT0();
        __syncthreads();
        if (t + 1 < ntile) {
            uint32_t so = sb + AST + ((t + 1) & 1) * AST_BYTES;
            int j0n = (t + 1) * 64;
#pragma unroll
            for (int i = 0; i < 2; i++) {
                int idx = tid + i * 256;
                int r = idx >> 3, c = idx & 7;
                size_t g = bh_off + (size_t)(j0n + r) * DH_ + c * 8;
                uint32_t sw = SMEM_SWZ(r * 128 + c * 16);
                cp16(so + AK_H + sw, Kh_ + g);
                cp16(so + AK_L + sw, Kl_ + g);
                cp16(so + AV_H + sw, Vh_ + g);
                cp16(so + AV_L + sw, Vl_ + g);
            }
            CP_COMMIT();
        }

        const uint32_t so = sb + AST + (t & 1) * AST_BYTES;
        const int j0 = t * 64;

        float S[8][4];
#pragma unroll
        for (int i = 0; i < 8; i++)
#pragma unroll
            for (int j = 0; j < 4; j++) S[i][j] = 0.f;
#pragma unroll
        for (int s = 0; s < 4; s++) {
            uint32_t kh4[4][4], kl4[4][4];
#pragma unroll
            for (int g = 0; g < 4; g++) {
                uint32_t off = SMEM_SWZ((g * 16 + krow) * 128 + s * 32 + kco);
                ldsm4(kh4[g], so + AK_H + off);
                ldsm4(kl4[g], so + AK_L + off);
            }
#pragma unroll
            for (int g = 0; g < 4; g++) {
                mma16816(S[2 * g],     qh[s], kh4[g]);
                mma16816(S[2 * g + 1], qh[s], kh4[g] + 2);
            }
#pragma unroll
            for (int g = 0; g < 4; g++) {
                mma16816(S[2 * g],     qh[s], kl4[g]);
                mma16816(S[2 * g + 1], qh[s], kl4[g] + 2);
            }
            uint32_t qlr[4];
            ldsm4(qlr, sb + AQ_L + SMEM_SWZ(a_row * 128 + s * 32 + a_co));
#pragma unroll
            for (int g = 0; g < 4; g++) {
                mma16816(S[2 * g],     qlr, kh4[g]);
                mma16816(S[2 * g + 1], qlr, kh4[g] + 2);
            }
        }

        if (j0 + 64 > len) {
            int kb0 = j0 + 2 * (lane & 3);
#pragma unroll
            for (int j = 0; j < 8; j++) {
#pragma unroll
                for (int e = 0; e < 4; e++) {
                    int kk = kb0 + 8 * j + (e & 1);
                    S[j][e] = (kk < len) ? S[j][e] * 0.125f : -1e9f;
                }
            }
        } else {
#pragma unroll
            for (int j = 0; j < 8; j++)
#pragma unroll
                for (int e = 0; e < 4; e++) S[j][e] *= 0.125f;
        }

        float mx0 = -1e30f, mx1 = -1e30f;
#pragma unroll
        for (int j = 0; j < 8; j++) {
            mx0 = fmaxf(mx0, fmaxf(S[j][0], S[j][1]));
            mx1 = fmaxf(mx1, fmaxf(S[j][2], S[j][3]));
        }
        mx0 = fmaxf(mx0, __shfl_xor_sync(0xffffffffu, mx0, 1));
        mx0 = fmaxf(mx0, __shfl_xor_sync(0xffffffffu, mx0, 2));
        mx1 = fmaxf(mx1, __shfl_xor_sync(0xffffffffu, mx1, 1));
        mx1 = fmaxf(mx1, __shfl_xor_sync(0xffffffffu, mx1, 2));
        float mn0 = fmaxf(m0, mx0), mn1 = fmaxf(m1, mx1);
        float f0 = __expf(m0 - mn0), f1 = __expf(m1 - mn1);
        l0 *= f0; l1 *= f1;
#pragma unroll
        for (int i = 0; i < 8; i++) {
            oa[i][0] *= f0; oa[i][1] *= f0; oa[i][2] *= f1; oa[i][3] *= f1;
        }
        float rs0 = 0.f, rs1 = 0.f;
#pragma unroll
        for (int j = 0; j < 8; j++) {
            S[j][0] = __expf(S[j][0] - mn0);
            S[j][1] = __expf(S[j][1] - mn0);
            S[j][2] = __expf(S[j][2] - mn1);
            S[j][3] = __expf(S[j][3] - mn1);
            rs0 += S[j][0] + S[j][1];
            rs1 += S[j][2] + S[j][3];
        }
        rs0 += __shfl_xor_sync(0xffffffffu, rs0, 1);
        rs0 += __shfl_xor_sync(0xffffffffu, rs0, 2);
        rs1 += __shfl_xor_sync(0xffffffffu, rs1, 1);
        rs1 += __shfl_xor_sync(0xffffffffu, rs1, 2);
        l0 += rs0; l1 += rs1;
        m0 = mn0; m1 = mn1;

#pragma unroll
        for (int s = 0; s < 4; s++) {
            uint32_t pah[4], pal[4];
#pragma unroll
            for (int half = 0; half < 2; half++) {
                const float* Sf = S[2 * s + half];
                __nv_bfloat162 hp0 = __floats2bfloat162_rn(Sf[0], Sf[1]);
                float2 hf0 = __bfloat1622float2(hp0);
                __nv_bfloat162 lp0 = __floats2bfloat162_rn(Sf[0] - hf0.x, Sf[1] - hf0.y);
                __nv_bfloat162 hp1 = __floats2bfloat162_rn(Sf[2], Sf[3]);
                float2 hf1 = __bfloat1622float2(hp1);
                __nv_bfloat162 lp1 = __floats2bfloat162_rn(Sf[2] - hf1.x, Sf[3] - hf1.y);
                pah[2 * half]     = *(uint32_t*)&hp0;
                pah[2 * half + 1] = *(uint32_t*)&hp1;
                pal[2 * half]     = *(uint32_t*)&lp0;
                pal[2 * half + 1] = *(uint32_t*)&lp1;
            }
            uint32_t vh4[4][4], vl4[4][4];
#pragma unroll
            for (int g = 0; g < 4; g++) {
                uint32_t off = SMEM_SWZ((s * 16 + vrow) * 128 + g * 32 + vco);
                ldsm4t(vh4[g], so + AV_H + off);
                ldsm4t(vl4[g], so + AV_L + off);
            }
#pragma unroll
            for (int g = 0; g < 4; g++) {
                mma16816(oa[2 * g],     pah, vh4[g]);
                mma16816(oa[2 * g + 1], pah, vh4[g] + 2);
            }
#pragma unroll
            for (int g = 0; g < 4; g++) {
                mma16816(oa[2 * g],     pah, vl4[g]);
                mma16816(oa[2 * g + 1], pah, vl4[g] + 2);
            }
#pragma unroll
            for (int g = 0; g < 4; g++) {
                mma16816(oa[2 * g],     pal, vh4[g]);
                mma16816(oa[2 * g + 1], pal, vh4[g] + 2);
            }
        }
    }

    float il0 = 1.f / l0, il1 = 1.f / l1;
    int qrow = q0 + wid * 16 + (lane >> 2);
    size_t base0 = ((size_t)b * S_ + qrow) * D_ + h * DH_ + 2 * (lane & 3);
    size_t base1 = base0 + (size_t)8 * D_;
#pragma unroll
    for (int nf = 0; nf < 8; nf++) {
        float e0 = oa[nf][0] * il0, e1 = oa[nf][1] * il0;
        float e2 = oa[nf][2] * il1, e3 = oa[nf][3] * il1;
        __nv_bfloat162 hp0 = __floats2bfloat162_rn(e0, e1);
        float2 hf0 = __bfloat1622float2(hp0);
        __nv_bfloat162 lp0 = __floats2bfloat162_rn(e0 - hf0.x, e1 - hf0.y);
        __nv_bfloat162 hp1 = __floats2bfloat162_rn(e2, e3);
        float2 hf1 = __bfloat1622float2(hp1);
        __nv_bfloat162 lp1 = __floats2bfloat162_rn(e2 - hf1.x, e3 - hf1.y);
        *(__nv_bfloat162*)(Oh_ + base0 + 8 * nf) = hp0;
        *(__nv_bfloat162*)(Ol_ + base0 + 8 * nf) = lp0;
        *(__nv_bfloat162*)(Oh_ + base1 + 8 * nf) = hp1;
        *(__nv_bfloat162*)(Ol_ + base1 + 8 * nf) = lp1;
    }
}

// ---------------------------------------------------------------------------
// fp32 -> split bf16 (row-major, for input v)
// ---------------------------------------------------------------------------
__global__ __launch_bounds__(256) void split_bf16_kernel(
    const float4* __restrict__ x, __nv_bfloat162* __restrict__ hi,
    __nv_bfloat162* __restrict__ lo, int n4)
{
    int i = blockIdx.x * blockDim.x + threadIdx.x;
    if (i >= n4) return;
    float4 v = x[i];
    __nv_bfloat162 a = __floats2bfloat162_rn(v.x, v.y);
    __nv_bfloat162 b = __floats2bfloat162_rn(v.z, v.w);
    float2 fa = __bfloat1622float2(a), fb = __bfloat1622float2(b);
    __nv_bfloat162 c = __floats2bfloat162_rn(v.x - fa.x, v.y - fa.y);
    __nv_bfloat162 d = __floats2bfloat162_rn(v.z - fb.x, v.w - fb.y);
    hi[2 * i] = a; hi[2 * i + 1] = b;
    lo[2 * i] = c; lo[2 * i + 1] = d;
}

// ---------------------------------------------------------------------------
// All 4 weights: W[K,N] fp32 -> concat W^T[4096][1024] split bf16
// ---------------------------------------------------------------------------
__global__ __launch_bounds__(256) void transpose_split4(
    const float* __restrict__ W0, const float* __restrict__ W1,
    const float* __restrict__ W2, const float* __restrict__ W3,
    __nv_bfloat16* __restrict__ Th, __nv_bfloat16* __restrict__ Tl)
{
    __shared__ float t[32][33];
    const int z = blockIdx.z;
    const float* W = (z == 0) ? W0 : (z == 1) ? W1 : (z == 2) ? W2 : W3;
    const int n0 = blockIdx.x * 32, k0 = blockIdx.y * 32;
    const int tx = threadIdx.x, ty = threadIdx.y;
#pragma unroll
    for (int i = 0; i < 4; i++)
        t[ty + i * 8][tx] = W[(size_t)(k0 + ty + i * 8) * D_ + n0 + tx];
    __syncthreads();
#pragma unroll
    for (int i = 0; i < 4; i++) {
        int n = z * D_ + n0 + ty + i * 8;
        float v = t[tx][ty + i * 8];
        __nv_bfloat16 h = __float2bfloat16(v);
        __nv_bfloat16 l = __float2bfloat16(v - __bfloat162float(h));
        Th[(size_t)n * D_ + k0 + tx] = h;
        Tl[(size_t)n * D_ + k0 + tx] = l;
    }
}

// ---------------------------------------------------------------------------
// Launch
// ---------------------------------------------------------------------------
extern "C" void kernel_launch(void* const* d_in, const int* in_sizes, int n_in,
                              void* d_out, int out_size)
{
    (void)in_sizes; (void)n_in; (void)out_size;
    const float* v       = (const float*)d_in[0];
    const int*   lengths = (const int*)  d_in[1];
    const float* Wq      = (const float*)d_in[2];
    const float* bq      = (const float*)d_in[3];
    const float* Wk      = (const float*)d_in[4];
    const float* bk      = (const float*)d_in[5];
    const float* Wv      = (const float*)d_in[6];
    const float* bv      = (const float*)d_in[7];
    const float* Wo      = (const float*)d_in[8];
    const float* bo      = (const float*)d_in[9];
    float* out = (float*)d_out;

    __nv_bfloat16 *ah, *al, *bh, *bl, *qh, *ql, *kh, *kl, *vh, *vl;
    cudaGetSymbolAddress((void**)&ah, g_Ah);
    cudaGetSymbolAddress((void**)&al, g_Al);
    cudaGetSymbolAddress((void**)&bh, g_Bh);
    cudaGetSymbolAddress((void**)&bl, g_Bl);
    cudaGetSymbolAddress((void**)&qh, g_Qh);
    cudaGetSymbolAddress((void**)&ql, g_Ql);
    cudaGetSymbolAddress((void**)&kh, g_Kh);
    cudaGetSymbolAddress((void**)&kl, g_Kl);
    cudaGetSymbolAddress((void**)&vh, g_Vh);
    cudaGetSymbolAddress((void**)&vl, g_Vl);

    cudaFuncSetAttribute(gemm_qkv, cudaFuncAttributeMaxDynamicSharedMemorySize, GEMM_SMEM);
    cudaFuncSetAttribute(gemm_out, cudaFuncAttributeMaxDynamicSharedMemorySize, GEMM_SMEM);
    cudaFuncSetAttribute(attn_mma, cudaFuncAttributeMaxDynamicSharedMemorySize, ATTN_SMEM);

    const int n4 = M_ * D_ / 4;
    dim3 gsplit((n4 + 255) / 256);
    dim3 gtr(32, 32, 4), btr(32, 8);

    transpose_split4<<<gtr, btr>>>(Wq, Wk, Wv, Wo, bh, bl);
    split_bf16_kernel<<<gsplit, 256>>>((const float4*)v,
        (__nv_bfloat162*)ah, (__nv_bfloat162*)al, n4);

    dim3 gqkv(3 * D_ / 128, M_ / 128);   // (24, 64)
    gemm_qkv<<<gqkv, 256, GEMM_SMEM>>>(ah, al, bh, bl, bq, bk, bv,
                                       qh, ql, kh, kl, vh, vl, lengths);

    dim3 ga(S_ / 128, H_, B_);           // (4, 16, 16)
    attn_mma<<<ga, 256, ATTN_SMEM>>>(qh, ql, kh, kl, vh, vl, lengths, ah, al);

    dim3 go(D_ / 128, M_ / 128);         // (8, 64)
    gemm_out<<<go, 256, GEMM_SMEM>>>(ah, al,
                                     bh + (size_t)3 * D_ * D_,
                                     bl + (size_t)3 * D_ * D_, bo, out);
}

// round 11
// speedup vs baseline: 1.6494x; 1.4553x over previous
#include <cuda_runtime.h>
#include <cuda_fp16.h>
#include <cstdint>
#include <cstddef>

// Problem constants
#define B_  16
#define S_  512
#define D_  1024
#define H_  16
#define DH_ 64
#define M_  (B_ * S_)   // 8192

// ---------------------------------------------------------------------------
// Scratch (static device globals), all fp16 now
// ---------------------------------------------------------------------------
__device__ __align__(128) __half g_X [M_ * D_];      // v (fp16), later attn out (row-major)
__device__ __align__(128) __half g_Bh[4 * D_ * D_];  // concat W^T hi [4096][1024] (Q,K,V,O)
__device__ __align__(128) __half g_Bl[4 * D_ * D_];  // concat W^T lo
__device__ __align__(128) __half g_Q [M_ * D_];      // head-major [b,h,s,dh], single fp16
__device__ __align__(128) __half g_Kh[M_ * D_];
__device__ __align__(128) __half g_Kl[M_ * D_];
__device__ __align__(128) __half g_Vh[M_ * D_];
__device__ __align__(128) __half g_Vl[M_ * D_];

// ---------------------------------------------------------------------------
// PTX helpers (sm_80+ only; compute_103 lowering rejects sm_103a-only features)
// ---------------------------------------------------------------------------
__device__ __forceinline__ uint32_t smem_u32(const void* p) {
    uint32_t a;
    asm("{ .reg .u64 t; cvta.to.shared.u64 t, %1; cvt.u32.u64 %0, t; }" : "=r"(a) : "l"(p));
    return a;
}
__device__ __forceinline__ void cp16(uint32_t saddr, const void* gaddr) {
    asm volatile("cp.async.cg.shared.global [%0], [%1], 16;" :: "r"(saddr), "l"(gaddr) : "memory");
}
#define CP_COMMIT() asm volatile("cp.async.commit_group;" ::: "memory")
#define CP_WAIT0()  asm volatile("cp.async.wait_group 0;" ::: "memory")
#define CP_WAIT1()  asm volatile("cp.async.wait_group 1;" ::: "memory")
#define CP_WAIT2()  asm volatile("cp.async.wait_group 2;" ::: "memory")

__device__ __forceinline__ void ldsm4(uint32_t* r, uint32_t a) {
    asm volatile("ldmatrix.sync.aligned.m8n8.x4.shared.b16 {%0,%1,%2,%3}, [%4];"
                 : "=r"(r[0]), "=r"(r[1]), "=r"(r[2]), "=r"(r[3]) : "r"(a));
}
__device__ __forceinline__ void ldsm4t(uint32_t* r, uint32_t a) {
    asm volatile("ldmatrix.sync.aligned.m8n8.x4.trans.shared.b16 {%0,%1,%2,%3}, [%4];"
                 : "=r"(r[0]), "=r"(r[1]), "=r"(r[2]), "=r"(r[3]) : "r"(a));
}
// fp16 HMMA, fp32 accumulate
__device__ __forceinline__ void mma16816(float* c, const uint32_t* a, const uint32_t* b) {
    asm volatile(
        "mma.sync.aligned.m16n8k16.row.col.f32.f16.f16.f32 "
        "{%0,%1,%2,%3}, {%4,%5,%6,%7}, {%8,%9}, {%0,%1,%2,%3};"
        : "+f"(c[0]), "+f"(c[1]), "+f"(c[2]), "+f"(c[3])
        : "r"(a[0]), "r"(a[1]), "r"(a[2]), "r"(a[3]), "r"(b[0]), "r"(b[1]));
}

#define SMEM_SWZ(o)   ((o) ^ (((o) >> 3) & 0x70))   // 128B rows
#define SMEM_SWZ32(o) ((o) ^ (((o) >> 3) & 0x30))   // 64B rows (BK=32)

// ---------------------------------------------------------------------------
// GEMM: C = Ah @ (Bh + Bl)^T (+bias), 2 MMA terms (A single fp16, B split).
// CTA tile 128x128, BK=32, 3-stage cp.async, 8 warps 2x4, 2 CTAs/SM.
// ---------------------------------------------------------------------------
#define T_AH 0
#define T_BH 8192
#define T_BL 16384
#define STAGE_BYTES 24576
#define GEMM_SMEM (3 * STAGE_BYTES)   // 73728

__device__ __forceinline__ void load_tile32(uint32_t sdst, const __half* g,
                                            int row0, int kc, int tid) {
#pragma unroll
    for (int i = 0; i < 2; i++) {
        int idx = tid + i * 256;          // 512 transfers of 16B
        int r = idx >> 2, c = idx & 3;    // 128 rows x 4 chunks
        const __half* gp = g + (size_t)(row0 + r) * D_ + kc * 32 + c * 8;
        cp16(sdst + SMEM_SWZ32(r * 64 + c * 16), gp);
    }
}

__device__ __forceinline__ void gemm_mainloop(
    uint32_t sb, const __half* A,
    const __half* Bhp, const __half* Blp,
    int m0, int tid, int wid, int lane, float acc[4][4][4])
{
    const int wm = (wid >> 2) * 64;
    const int wn = (wid & 3) * 32;
    const int a_row = wm + (lane & 15);
    const int a_coff = (lane >> 4) * 16;
    const int b_row = wn + ((lane >> 4) << 3) + (lane & 7);
    const int b_coff = ((lane >> 3) & 1) * 16;

#pragma unroll
    for (int p = 0; p < 2; p++) {
        uint32_t so = sb + p * STAGE_BYTES;
        load_tile32(so + T_AH, A, m0, p, tid);
        load_tile32(so + T_BH, Bhp, 0, p, tid);
        load_tile32(so + T_BL, Blp, 0, p, tid);
        CP_COMMIT();
    }

    int stage = 0, nstage = 2;
#pragma unroll 1
    for (int c = 0; c < 32; c++) {
        if (c + 2 < 32) {
            uint32_t so = sb + nstage * STAGE_BYTES;
            load_tile32(so + T_AH, A, m0, c + 2, tid);
            load_tile32(so + T_BH, Bhp, 0, c + 2, tid);
            load_tile32(so + T_BL, Blp, 0, c + 2, tid);
            CP_COMMIT();
            CP_WAIT2();
        } else if (c + 1 < 32) {
            CP_WAIT1();
        } else {
            CP_WAIT0();
        }
        __syncthreads();

        const uint32_t so = sb + stage * STAGE_BYTES;
#pragma unroll
        for (int ks = 0; ks < 2; ks++) {
            const int kb = ks * 32;
            uint32_t ah[4][4], bh[2][4], bl[2][4];
#pragma unroll
            for (int mt = 0; mt < 4; mt++) {
                uint32_t off = SMEM_SWZ32((a_row + mt * 16) * 64 + kb + a_coff);
                ldsm4(ah[mt], so + T_AH + off);
            }
#pragma unroll
            for (int nt2 = 0; nt2 < 2; nt2++) {
                uint32_t off = SMEM_SWZ32((b_row + nt2 * 16) * 64 + kb + b_coff);
                ldsm4(bh[nt2], so + T_BH + off);
                ldsm4(bl[nt2], so + T_BL + off);
            }
#pragma unroll
            for (int mt = 0; mt < 4; mt++)
#pragma unroll
                for (int nt = 0; nt < 4; nt++)
                    mma16816(acc[mt][nt], ah[mt], &bh[nt >> 1][(nt & 1) * 2]);
#pragma unroll
            for (int mt = 0; mt < 4; mt++)
#pragma unroll
                for (int nt = 0; nt < 4; nt++)
                    mma16816(acc[mt][nt], ah[mt], &bl[nt >> 1][(nt & 1) * 2]);
        }
        __syncthreads();
        stage = (stage + 1) == 3 ? 0 : stage + 1;
        nstage = (nstage + 1) == 3 ? 0 : nstage + 1;
    }
}

// ---------------------------------------------------------------------------
// Fused QKV projection GEMM: grid (24, 64); proj = n0>>10. K/V skip by length.
// Q stored single fp16 head-major; K/V stored split fp16 head-major.
// ---------------------------------------------------------------------------
__global__ __launch_bounds__(256, 2) void gemm_qkv(
    const __half* __restrict__ A,
    const __half* __restrict__ Bh, const __half* __restrict__ Bl,
    const float* __restrict__ bq, const float* __restrict__ bk, const float* __restrict__ bv,
    __half* __restrict__ q1,
    __half* __restrict__ kh, __half* __restrict__ kl,
    __half* __restrict__ vh, __half* __restrict__ vl,
    const int* __restrict__ lengths)
{
    extern __shared__ __align__(1024) char smem[];
    const int tid  = threadIdx.x;
    const int wid  = tid >> 5, lane = tid & 31;
    const int m0   = blockIdx.y * 128;
    const int n0   = blockIdx.x * 128;
    const int proj = n0 >> 10;

    if (proj != 0) {
        int len = lengths[m0 >> 9];
        if ((m0 & 511) >= ((len + 63) & ~63)) return;
    }

    const float* bias = (proj == 0) ? bq : (proj == 1) ? bk : bv;
    __half* Ch = (proj == 0) ? q1 : (proj == 1) ? kh : vh;
    __half* Cl = (proj == 1) ? kl : vl;   // unused for proj==0

    uint32_t sb = smem_u32(smem);
    float acc[4][4][4];
#pragma unroll
    for (int i = 0; i < 4; i++)
#pragma unroll
        for (int j = 0; j < 4; j++)
#pragma unroll
            for (int k = 0; k < 4; k++) acc[i][j][k] = 0.f;

    gemm_mainloop(sb, A, Bh + (size_t)n0 * D_, Bl + (size_t)n0 * D_,
                  m0, tid, wid, lane, acc);

    const int wm = (wid >> 2) * 64;
    const int wn = (wid & 3) * 32;
    const int er = lane >> 2;
    const int ec = (lane & 3) * 2;
#pragma unroll
    for (int mt = 0; mt < 4; mt++) {
#pragma unroll
        for (int nt = 0; nt < 4; nt++) {
            int row = m0 + wm + mt * 16 + er;
            int lc  = (n0 & 1023) + wn + nt * 8 + ec;
            float b0 = bias[lc], b1 = bias[lc + 1];
            float o0 = acc[mt][nt][0] + b0, o1 = acc[mt][nt][1] + b1;
            float o2 = acc[mt][nt][2] + b0, o3 = acc[mt][nt][3] + b1;
            int bb = row >> 9, ss = row & 511, hh = lc >> 6, dd = lc & 63;
            size_t base = (((size_t)bb * H_ + hh) * S_ + ss) * DH_ + dd;
            __half2 hp  = __floats2half2_rn(o0, o1);
            __half2 hp2 = __floats2half2_rn(o2, o3);
            *(__half2*)(Ch + base) = hp;
            *(__half2*)(Ch + base + 8 * DH_) = hp2;
            if (proj != 0) {
                float2 hf  = __half22float2(hp);
                float2 hf2 = __half22float2(hp2);
                *(__half2*)(Cl + base) = __floats2half2_rn(o0 - hf.x, o1 - hf.y);
                *(__half2*)(Cl + base + 8 * DH_) = __floats2half2_rn(o2 - hf2.x, o3 - hf2.y);
            }
        }
    }
}

// ---------------------------------------------------------------------------
// Output projection GEMM: out = A @ Wo^T + bo (fp32 row-major), grid (8, 64)
// ---------------------------------------------------------------------------
__global__ __launch_bounds__(256, 2) void gemm_out(
    const __half* __restrict__ A,
    const __half* __restrict__ Bh, const __half* __restrict__ Bl,
    const float* __restrict__ bias, float* __restrict__ C)
{
    extern __shared__ __align__(1024) char smem[];
    const int tid  = threadIdx.x;
    const int wid  = tid >> 5, lane = tid & 31;
    const int m0   = blockIdx.y * 128;
    const int n0   = blockIdx.x * 128;

    uint32_t sb = smem_u32(smem);
    float acc[4][4][4];
#pragma unroll
    for (int i = 0; i < 4; i++)
#pragma unroll
        for (int j = 0; j < 4; j++)
#pragma unroll
            for (int k = 0; k < 4; k++) acc[i][j][k] = 0.f;

    gemm_mainloop(sb, A, Bh + (size_t)n0 * D_, Bl + (size_t)n0 * D_,
                  m0, tid, wid, lane, acc);

    const int wm = (wid >> 2) * 64;
    const int wn = (wid & 3) * 32;
    const int er = lane >> 2;
    const int ec = (lane & 3) * 2;
#pragma unroll
    for (int mt = 0; mt < 4; mt++) {
#pragma unroll
        for (int nt = 0; nt < 4; nt++) {
            int row = m0 + wm + mt * 16 + er;
            int col = n0 + wn + nt * 8 + ec;
            float b0 = bias[col], b1 = bias[col + 1];
            float2 p0 = make_float2(acc[mt][nt][0] + b0, acc[mt][nt][1] + b1);
            float2 p1 = make_float2(acc[mt][nt][2] + b0, acc[mt][nt][3] + b1);
            *(float2*)(C + (size_t)row * D_ + col) = p0;
            *(float2*)(C + (size_t)(row + 8) * D_ + col) = p1;
        }
    }
}

// ---------------------------------------------------------------------------
// HMMA flash attention, 2-term fp16: S = Q@(Kh+Kl)^T, O = P@(Vh+Vl).
// Q and P single fp16. CTA = one (b,h) x 128 q rows. 64-key tiles, 2-stage.
// Writes single fp16 row-major [M][D] for the O projection.
// ---------------------------------------------------------------------------
#define AQ   0
#define AST  16384
#define AK_H 0
#define AK_L 8192
#define AV_H 16384
#define AV_L 24576
#define AST_BYTES 32768
#define ATTN_SMEM (16384 + 2 * AST_BYTES)   // 81920

__global__ __launch_bounds__(256, 2) void attn_mma(
    const __half* __restrict__ Q_,
    const __half* __restrict__ Kh_, const __half* __restrict__ Kl_,
    const __half* __restrict__ Vh_, const __half* __restrict__ Vl_,
    const int* __restrict__ lengths,
    __half* __restrict__ O_)
{
    extern __shared__ __align__(1024) char smem[];
    const int tid = threadIdx.x, wid = tid >> 5, lane = tid & 31;
    const int b = blockIdx.z, h = blockIdx.y, q0 = blockIdx.x * 128;
    const int len = lengths[b];
    uint32_t sb = smem_u32(smem);
    const size_t bh_off = ((size_t)b * H_ + h) * (S_ * DH_);

    // Q tile load (128 rows x 128B, single)
#pragma unroll
    for (int i = 0; i < 4; i++) {
        int idx = tid + i * 256;
        int r = idx >> 3, c = idx & 7;
        cp16(sb + AQ + SMEM_SWZ(r * 128 + c * 16), Q_ + bh_off + (size_t)(q0 + r) * DH_ + c * 8);
    }
    CP_COMMIT();

    const int jend = (len + 63) & ~63;
    const int ntile = jend >> 6;

    // prefetch KV tile 0 -> stage 0
    {
        uint32_t so = sb + AST;
#pragma unroll
        for (int i = 0; i < 2; i++) {
            int idx = tid + i * 256;
            int r = idx >> 3, c = idx & 7;
            size_t g = bh_off + (size_t)r * DH_ + c * 8;
            uint32_t sw = SMEM_SWZ(r * 128 + c * 16);
            cp16(so + AK_H + sw, Kh_ + g);
            cp16(so + AK_L + sw, Kl_ + g);
            cp16(so + AV_H + sw, Vh_ + g);
            cp16(so + AV_L + sw, Vl_ + g);
        }
        CP_COMMIT();
    }

    CP_WAIT1();
    __syncthreads();

    const int a_row = wid * 16 + (lane & 15);
    const int a_co = (lane >> 4) * 16;
    uint32_t qh[4][4];
#pragma unroll
    for (int s = 0; s < 4; s++) {
        uint32_t off = SMEM_SWZ(a_row * 128 + s * 32 + a_co);
        ldsm4(qh[s], sb + AQ + off);
    }

    float oa[8][4];
#pragma unroll
    for (int i = 0; i < 8; i++)
#pragma unroll
        for (int j = 0; j < 4; j++) oa[i][j] = 0.f;
    float m0 = -1e30f, m1 = -1e30f, l0 = 0.f, l1 = 0.f;

    const int krow = ((lane >> 4) << 3) + (lane & 7);
    const int kco  = ((lane >> 3) & 1) * 16;
    const int vrow = lane & 15;
    const int vco  = (lane >> 4) * 16;

#pragma unroll 1
    for (int t = 0; t < ntile; t++) {
        CP_WAIT0();
        __syncthreads();
        if (t + 1 < ntile) {
            uint32_t so = sb + AST + ((t + 1) & 1) * AST_BYTES;
            int j0n = (t + 1) * 64;
#pragma unroll
            for (int i = 0; i < 2; i++) {
                int idx = tid + i * 256;
                int r = idx >> 3, c = idx & 7;
                size_t g = bh_off + (size_t)(j0n + r) * DH_ + c * 8;
                uint32_t sw = SMEM_SWZ(r * 128 + c * 16);
                cp16(so + AK_H + sw, Kh_ + g);
                cp16(so + AK_L + sw, Kl_ + g);
                cp16(so + AV_H + sw, Vh_ + g);
                cp16(so + AV_L + sw, Vl_ + g);
            }
            CP_COMMIT();
        }

        const uint32_t so = sb + AST + (t & 1) * AST_BYTES;
        const int j0 = t * 64;

        // ---- S = Q @ (Kh+Kl)^T : 2 terms ----
        float S[8][4];
#pragma unroll
        for (int i = 0; i < 8; i++)
#pragma unroll
            for (int j = 0; j < 4; j++) S[i][j] = 0.f;
#pragma unroll
        for (int s = 0; s < 4; s++) {
            uint32_t kh4[4][4], kl4[4][4];
#pragma unroll
            for (int g = 0; g < 4; g++) {
                uint32_t off = SMEM_SWZ((g * 16 + krow) * 128 + s * 32 + kco);
                ldsm4(kh4[g], so + AK_H + off);
                ldsm4(kl4[g], so + AK_L + off);
            }
#pragma unroll
            for (int g = 0; g < 4; g++) {
                mma16816(S[2 * g],     qh[s], kh4[g]);
                mma16816(S[2 * g + 1], qh[s], kh4[g] + 2);
            }
#pragma unroll
            for (int g = 0; g < 4; g++) {
                mma16816(S[2 * g],     qh[s], kl4[g]);
                mma16816(S[2 * g + 1], qh[s], kl4[g] + 2);
            }
        }

        // ---- scale + mask ----
        if (j0 + 64 > len) {
            int kb0 = j0 + 2 * (lane & 3);
#pragma unroll
            for (int j = 0; j < 8; j++) {
#pragma unroll
                for (int e = 0; e < 4; e++) {
                    int kk = kb0 + 8 * j + (e & 1);
                    S[j][e] = (kk < len) ? S[j][e] * 0.125f : -1e9f;
                }
            }
        } else {
#pragma unroll
            for (int j = 0; j < 8; j++)
#pragma unroll
                for (int e = 0; e < 4; e++) S[j][e] *= 0.125f;
        }

        // ---- online softmax ----
        float mx0 = -1e30f, mx1 = -1e30f;
#pragma unroll
        for (int j = 0; j < 8; j++) {
            mx0 = fmaxf(mx0, fmaxf(S[j][0], S[j][1]));
            mx1 = fmaxf(mx1, fmaxf(S[j][2], S[j][3]));
        }
        mx0 = fmaxf(mx0, __shfl_xor_sync(0xffffffffu, mx0, 1));
        mx0 = fmaxf(mx0, __shfl_xor_sync(0xffffffffu, mx0, 2));
        mx1 = fmaxf(mx1, __shfl_xor_sync(0xffffffffu, mx1, 1));
        mx1 = fmaxf(mx1, __shfl_xor_sync(0xffffffffu, mx1, 2));
        float mn0 = fmaxf(m0, mx0), mn1 = fmaxf(m1, mx1);
        float f0 = __expf(m0 - mn0), f1 = __expf(m1 - mn1);
        l0 *= f0; l1 *= f1;
#pragma unroll
        for (int i = 0; i < 8; i++) {
            oa[i][0] *= f0; oa[i][1] *= f0; oa[i][2] *= f1; oa[i][3] *= f1;
        }
        float rs0 = 0.f, rs1 = 0.f;
#pragma unroll
        for (int j = 0; j < 8; j++) {
            S[j][0] = __expf(S[j][0] - mn0);
            S[j][1] = __expf(S[j][1] - mn0);
            S[j][2] = __expf(S[j][2] - mn1);
            S[j][3] = __expf(S[j][3] - mn1);
            rs0 += S[j][0] + S[j][1];
            rs1 += S[j][2] + S[j][3];
        }
        rs0 += __shfl_xor_sync(0xffffffffu, rs0, 1);
        rs0 += __shfl_xor_sync(0xffffffffu, rs0, 2);
        rs1 += __shfl_xor_sync(0xffffffffu, rs1, 1);
        rs1 += __shfl_xor_sync(0xffffffffu, rs1, 2);
        l0 += rs0; l1 += rs1;
        m0 = mn0; m1 = mn1;

        // ---- O += P @ (Vh+Vl) : 2 terms, P single fp16 ----
#pragma unroll
        for (int s = 0; s < 4; s++) {
            uint32_t pah[4];
#pragma unroll
            for (int half = 0; half < 2; half++) {
                const float* Sf = S[2 * s + half];
                __half2 hp0 = __floats2half2_rn(Sf[0], Sf[1]);
                __half2 hp1 = __floats2half2_rn(Sf[2], Sf[3]);
                pah[2 * half]     = *(uint32_t*)&hp0;
                pah[2 * half + 1] = *(uint32_t*)&hp1;
            }
            uint32_t vh4[4][4], vl4[4][4];
#pragma unroll
            for (int g = 0; g < 4; g++) {
                uint32_t off = SMEM_SWZ((s * 16 + vrow) * 128 + g * 32 + vco);
                ldsm4t(vh4[g], so + AV_H + off);
                ldsm4t(vl4[g], so + AV_L + off);
            }
#pragma unroll
            for (int g = 0; g < 4; g++) {
                mma16816(oa[2 * g],     pah, vh4[g]);
                mma16816(oa[2 * g + 1], pah, vh4[g] + 2);
            }
#pragma unroll
            for (int g = 0; g < 4; g++) {
                mma16816(oa[2 * g],     pah, vl4[g]);
                mma16816(oa[2 * g + 1], pah, vl4[g] + 2);
            }
        }
    }

    // ---- epilogue: normalize, write single fp16 row-major [M][D] ----
    float il0 = 1.f / l0, il1 = 1.f / l1;
    int qrow = q0 + wid * 16 + (lane >> 2);
    size_t base0 = ((size_t)b * S_ + qrow) * D_ + h * DH_ + 2 * (lane & 3);
    size_t base1 = base0 + (size_t)8 * D_;
#pragma unroll
    for (int nf = 0; nf < 8; nf++) {
        *(__half2*)(O_ + base0 + 8 * nf) = __floats2half2_rn(oa[nf][0] * il0, oa[nf][1] * il0);
        *(__half2*)(O_ + base1 + 8 * nf) = __floats2half2_rn(oa[nf][2] * il1, oa[nf][3] * il1);
    }
}

// ---------------------------------------------------------------------------
// fp32 -> fp16 (row-major, for input v)
// ---------------------------------------------------------------------------
__global__ __launch_bounds__(256) void tofp16_kernel(
    const float4* __restrict__ x, __half2* __restrict__ o, int n4)
{
    int i = blockIdx.x * blockDim.x + threadIdx.x;
    if (i >= n4) return;
    float4 v = x[i];
    o[2 * i]     = __floats2half2_rn(v.x, v.y);
    o[2 * i + 1] = __floats2half2_rn(v.z, v.w);
}

// ---------------------------------------------------------------------------
// All 4 weights: W[K,N] fp32 -> concat W^T[4096][1024] split fp16
// grid (32,32,4), block (32,8)
// ---------------------------------------------------------------------------
__global__ __launch_bounds__(256) void transpose_split4(
    const float* __restrict__ W0, const float* __restrict__ W1,
    const float* __restrict__ W2, const float* __restrict__ W3,
    __half* __restrict__ Th, __half* __restrict__ Tl)
{
    __shared__ float t[32][33];
    const int z = blockIdx.z;
    const float* W = (z == 0) ? W0 : (z == 1) ? W1 : (z == 2) ? W2 : W3;
    const int n0 = blockIdx.x * 32, k0 = blockIdx.y * 32;
    const int tx = threadIdx.x, ty = threadIdx.y;
#pragma unroll
    for (int i = 0; i < 4; i++)
        t[ty + i * 8][tx] = W[(size_t)(k0 + ty + i * 8) * D_ + n0 + tx];
    __syncthreads();
#pragma unroll
    for (int i = 0; i < 4; i++) {
        int n = z * D_ + n0 + ty + i * 8;
        float v = t[tx][ty + i * 8];
        __half hv = __float2half_rn(v);
        __half lv = __float2half_rn(v - __half2float(hv));
        Th[(size_t)n * D_ + k0 + tx] = hv;
        Tl[(size_t)n * D_ + k0 + tx] = lv;
    }
}

// ---------------------------------------------------------------------------
// Launch
// ---------------------------------------------------------------------------
extern "C" void kernel_launch(void* const* d_in, const int* in_sizes, int n_in,
                              void* d_out, int out_size)
{
    (void)in_sizes; (void)n_in; (void)out_size;
    const float* v       = (const float*)d_in[0];
    const int*   lengths = (const int*)  d_in[1];
    const float* Wq      = (const float*)d_in[2];
    const float* bq      = (const float*)d_in[3];
    const float* Wk      = (const float*)d_in[4];
    const float* bk      = (const float*)d_in[5];
    const float* Wv      = (const float*)d_in[6];
    const float* bv      = (const float*)d_in[7];
    const float* Wo      = (const float*)d_in[8];
    const float* bo      = (const float*)d_in[9];
    float* out = (float*)d_out;

    __half *xb, *bh, *bl, *q1, *kh, *kl, *vh, *vl;
    cudaGetSymbolAddress((void**)&xb, g_X);
    cudaGetSymbolAddress((void**)&bh, g_Bh);
    cudaGetSymbolAddress((void**)&bl, g_Bl);
    cudaGetSymbolAddress((void**)&q1, g_Q);
    cudaGetSymbolAddress((void**)&kh, g_Kh);
    cudaGetSymbolAddress((void**)&kl, g_Kl);
    cudaGetSymbolAddress((void**)&vh, g_Vh);
    cudaGetSymbolAddress((void**)&vl, g_Vl);

    cudaFuncSetAttribute(gemm_qkv, cudaFuncAttributeMaxDynamicSharedMemorySize, GEMM_SMEM);
    cudaFuncSetAttribute(gemm_out, cudaFuncAttributeMaxDynamicSharedMemorySize, GEMM_SMEM);
    cudaFuncSetAttribute(attn_mma, cudaFuncAttributeMaxDynamicSharedMemorySize, ATTN_SMEM);

    const int n4 = M_ * D_ / 4;
    dim3 gsplit((n4 + 255) / 256);
    dim3 gtr(32, 32, 4), btr(32, 8);

    transpose_split4<<<gtr, btr>>>(Wq, Wk, Wv, Wo, bh, bl);
    tofp16_kernel<<<gsplit, 256>>>((const float4*)v, (__half2*)xb, n4);

    dim3 gqkv(3 * D_ / 128, M_ / 128);   // (24, 64)
    gemm_qkv<<<gqkv, 256, GEMM_SMEM>>>(xb, bh, bl, bq, bk, bv,
                                       q1, kh, kl, vh, vl, lengths);

    dim3 ga(S_ / 128, H_, B_);           // (4, 16, 16)
    attn_mma<<<ga, 256, ATTN_SMEM>>>(q1, kh, kl, vh, vl, lengths, xb);

    dim3 go(D_ / 128, M_ / 128);         // (8, 64)
    gemm_out<<<go, 256, GEMM_SMEM>>>(xb,
                                     bh + (size_t)3 * D_ * D_,
                                     bl + (size_t)3 * D_ * D_, bo, out);
}

// round 12
// speedup vs baseline: 2.5983x; 1.5753x over previous
#include <cuda_runtime.h>
#include <cuda_fp16.h>
#include <cstdint>
#include <cstddef>

// Problem constants
#define B_  16
#define S_  512
#define D_  1024
#define H_  16
#define DH_ 64
#define M_  (B_ * S_)   // 8192

// ---------------------------------------------------------------------------
// Scratch (static device globals), all single fp16
// ---------------------------------------------------------------------------
__device__ __align__(128) __half g_X[M_ * D_];      // v (fp16), later attn out (row-major)
__device__ __align__(128) __half g_B[4 * D_ * D_];  // concat W^T [4096][1024] (Q,K,V,O)
__device__ __align__(128) __half g_Q[M_ * D_];      // head-major [b,h,s,dh]
__device__ __align__(128) __half g_K[M_ * D_];
__device__ __align__(128) __half g_V[M_ * D_];

// ---------------------------------------------------------------------------
// PTX helpers (sm_80+ only; compute_103 lowering rejects sm_103a-only features)
// ---------------------------------------------------------------------------
__device__ __forceinline__ uint32_t smem_u32(const void* p) {
    uint32_t a;
    asm("{ .reg .u64 t; cvta.to.shared.u64 t, %1; cvt.u32.u64 %0, t; }" : "=r"(a) : "l"(p));
    return a;
}
__device__ __forceinline__ void cp16(uint32_t saddr, const void* gaddr) {
    asm volatile("cp.async.cg.shared.global [%0], [%1], 16;" :: "r"(saddr), "l"(gaddr) : "memory");
}
#define CP_COMMIT() asm volatile("cp.async.commit_group;" ::: "memory")
#define CP_WAIT0()  asm volatile("cp.async.wait_group 0;" ::: "memory")
#define CP_WAIT1()  asm volatile("cp.async.wait_group 1;" ::: "memory")
#define CP_WAIT2()  asm volatile("cp.async.wait_group 2;" ::: "memory")

__device__ __forceinline__ void ldsm4(uint32_t* r, uint32_t a) {
    asm volatile("ldmatrix.sync.aligned.m8n8.x4.shared.b16 {%0,%1,%2,%3}, [%4];"
                 : "=r"(r[0]), "=r"(r[1]), "=r"(r[2]), "=r"(r[3]) : "r"(a));
}
__device__ __forceinline__ void ldsm4t(uint32_t* r, uint32_t a) {
    asm volatile("ldmatrix.sync.aligned.m8n8.x4.trans.shared.b16 {%0,%1,%2,%3}, [%4];"
                 : "=r"(r[0]), "=r"(r[1]), "=r"(r[2]), "=r"(r[3]) : "r"(a));
}
// fp16 HMMA, fp32 accumulate
__device__ __forceinline__ void mma16816(float* c, const uint32_t* a, const uint32_t* b) {
    asm volatile(
        "mma.sync.aligned.m16n8k16.row.col.f32.f16.f16.f32 "
        "{%0,%1,%2,%3}, {%4,%5,%6,%7}, {%8,%9}, {%0,%1,%2,%3};"
        : "+f"(c[0]), "+f"(c[1]), "+f"(c[2]), "+f"(c[3])
        : "r"(a[0]), "r"(a[1]), "r"(a[2]), "r"(a[3]), "r"(b[0]), "r"(b[1]));
}

#define SMEM_SWZ(o)   ((o) ^ (((o) >> 3) & 0x70))   // 128B rows
#define SMEM_SWZ32(o) ((o) ^ (((o) >> 3) & 0x30))   // 64B rows (BK=32)

// ---------------------------------------------------------------------------
// GEMM: C = A @ B^T (+bias), single fp16, fp32 accum.
// CTA tile 128x128, BK=32, 3-stage cp.async, 8 warps 2x4, 2 CTAs/SM.
// ---------------------------------------------------------------------------
#define T_A 0
#define T_B 8192
#define STAGE_BYTES 16384
#define GEMM_SMEM (3 * STAGE_BYTES)   // 49152

__device__ __forceinline__ void load_tile32(uint32_t sdst, const __half* g,
                                            int row0, int kc, int tid) {
#pragma unroll
    for (int i = 0; i < 2; i++) {
        int idx = tid + i * 256;          // 512 transfers of 16B
        int r = idx >> 2, c = idx & 3;    // 128 rows x 4 chunks
        const __half* gp = g + (size_t)(row0 + r) * D_ + kc * 32 + c * 8;
        cp16(sdst + SMEM_SWZ32(r * 64 + c * 16), gp);
    }
}

__device__ __forceinline__ void gemm_mainloop(
    uint32_t sb, const __half* A, const __half* Bp,
    int m0, int tid, int wid, int lane, float acc[4][4][4])
{
    const int wm = (wid >> 2) * 64;
    const int wn = (wid & 3) * 32;
    const int a_row = wm + (lane & 15);
    const int a_coff = (lane >> 4) * 16;
    const int b_row = wn + ((lane >> 4) << 3) + (lane & 7);
    const int b_coff = ((lane >> 3) & 1) * 16;

#pragma unroll
    for (int p = 0; p < 2; p++) {
        uint32_t so = sb + p * STAGE_BYTES;
        load_tile32(so + T_A, A, m0, p, tid);
        load_tile32(so + T_B, Bp, 0, p, tid);
        CP_COMMIT();
    }

    int stage = 0, nstage = 2;
#pragma unroll 1
    for (int c = 0; c < 32; c++) {
        if (c + 2 < 32) {
            uint32_t so = sb + nstage * STAGE_BYTES;
            load_tile32(so + T_A, A, m0, c + 2, tid);
            load_tile32(so + T_B, Bp, 0, c + 2, tid);
            CP_COMMIT();
            CP_WAIT2();
        } else if (c + 1 < 32) {
            CP_WAIT1();
        } else {
            CP_WAIT0();
        }
        __syncthreads();

        const uint32_t so = sb + stage * STAGE_BYTES;
#pragma unroll
        for (int ks = 0; ks < 2; ks++) {
            const int kb = ks * 32;
            uint32_t ah[4][4], bh[2][4];
#pragma unroll
            for (int mt = 0; mt < 4; mt++) {
                uint32_t off = SMEM_SWZ32((a_row + mt * 16) * 64 + kb + a_coff);
                ldsm4(ah[mt], so + T_A + off);
            }
#pragma unroll
            for (int nt2 = 0; nt2 < 2; nt2++) {
                uint32_t off = SMEM_SWZ32((b_row + nt2 * 16) * 64 + kb + b_coff);
                ldsm4(bh[nt2], so + T_B + off);
            }
#pragma unroll
            for (int mt = 0; mt < 4; mt++)
#pragma unroll
                for (int nt = 0; nt < 4; nt++)
                    mma16816(acc[mt][nt], ah[mt], &bh[nt >> 1][(nt & 1) * 2]);
        }
        __syncthreads();
        stage = (stage + 1) == 3 ? 0 : stage + 1;
        nstage = (nstage + 1) == 3 ? 0 : nstage + 1;
    }
}

// ---------------------------------------------------------------------------
// Fused QKV projection GEMM: grid (24, 64); proj = n0>>10. K/V skip by length.
// All outputs single fp16 head-major [b,h,s,dh].
// ---------------------------------------------------------------------------
__global__ __launch_bounds__(256, 2) void gemm_qkv(
    const __half* __restrict__ A, const __half* __restrict__ Bc,
    const float* __restrict__ bq, const float* __restrict__ bk, const float* __restrict__ bv,
    __half* __restrict__ qo, __half* __restrict__ ko, __half* __restrict__ vo,
    const int* __restrict__ lengths)
{
    extern __shared__ __align__(1024) char smem[];
    const int tid  = threadIdx.x;
    const int wid  = tid >> 5, lane = tid & 31;
    const int m0   = blockIdx.y * 128;
    const int n0   = blockIdx.x * 128;
    const int proj = n0 >> 10;

    if (proj != 0) {
        int len = lengths[m0 >> 9];
        if ((m0 & 511) >= ((len + 63) & ~63)) return;
    }

    const float* bias = (proj == 0) ? bq : (proj == 1) ? bk : bv;
    __half* Co = (proj == 0) ? qo : (proj == 1) ? ko : vo;

    uint32_t sb = smem_u32(smem);
    float acc[4][4][4];
#pragma unroll
    for (int i = 0; i < 4; i++)
#pragma unroll
        for (int j = 0; j < 4; j++)
#pragma unroll
            for (int k = 0; k < 4; k++) acc[i][j][k] = 0.f;

    gemm_mainloop(sb, A, Bc + (size_t)n0 * D_, m0, tid, wid, lane, acc);

    const int wm = (wid >> 2) * 64;
    const int wn = (wid & 3) * 32;
    const int er = lane >> 2;
    const int ec = (lane & 3) * 2;
#pragma unroll
    for (int mt = 0; mt < 4; mt++) {
#pragma unroll
        for (int nt = 0; nt < 4; nt++) {
            int row = m0 + wm + mt * 16 + er;
            int lc  = (n0 & 1023) + wn + nt * 8 + ec;
            float b0 = bias[lc], b1 = bias[lc + 1];
            int bb = row >> 9, ss = row & 511, hh = lc >> 6, dd = lc & 63;
            size_t base = (((size_t)bb * H_ + hh) * S_ + ss) * DH_ + dd;
            *(__half2*)(Co + base) =
                __floats2half2_rn(acc[mt][nt][0] + b0, acc[mt][nt][1] + b1);
            *(__half2*)(Co + base + 8 * DH_) =
                __floats2half2_rn(acc[mt][nt][2] + b0, acc[mt][nt][3] + b1);
        }
    }
}

// ---------------------------------------------------------------------------
// Output projection GEMM: out = A @ Wo^T + bo (fp32 row-major), grid (8, 64)
// ---------------------------------------------------------------------------
__global__ __launch_bounds__(256, 2) void gemm_out(
    const __half* __restrict__ A, const __half* __restrict__ Bc,
    const float* __restrict__ bias, float* __restrict__ C)
{
    extern __shared__ __align__(1024) char smem[];
    const int tid  = threadIdx.x;
    const int wid  = tid >> 5, lane = tid & 31;
    const int m0   = blockIdx.y * 128;
    const int n0   = blockIdx.x * 128;

    uint32_t sb = smem_u32(smem);
    float acc[4][4][4];
#pragma unroll
    for (int i = 0; i < 4; i++)
#pragma unroll
        for (int j = 0; j < 4; j++)
#pragma unroll
            for (int k = 0; k < 4; k++) acc[i][j][k] = 0.f;

    gemm_mainloop(sb, A, Bc + (size_t)n0 * D_, m0, tid, wid, lane, acc);

    const int wm = (wid >> 2) * 64;
    const int wn = (wid & 3) * 32;
    const int er = lane >> 2;
    const int ec = (lane & 3) * 2;
#pragma unroll
    for (int mt = 0; mt < 4; mt++) {
#pragma unroll
        for (int nt = 0; nt < 4; nt++) {
            int row = m0 + wm + mt * 16 + er;
            int col = n0 + wn + nt * 8 + ec;
            float b0 = bias[col], b1 = bias[col + 1];
            float2 p0 = make_float2(acc[mt][nt][0] + b0, acc[mt][nt][1] + b1);
            float2 p1 = make_float2(acc[mt][nt][2] + b0, acc[mt][nt][3] + b1);
            *(float2*)(C + (size_t)row * D_ + col) = p0;
            *(float2*)(C + (size_t)(row + 8) * D_ + col) = p1;
        }
    }
}

// ---------------------------------------------------------------------------
// HMMA flash attention, pure fp16 operands, fp32 accum/softmax.
// CTA = one (b,h) x 128 q rows. 64-key tiles, 2-stage. Writes fp16 row-major.
// ---------------------------------------------------------------------------
#define AQ   0
#define AST  16384
#define AK   0
#define AV   8192
#define AST_BYTES 16384
#define ATTN_SMEM (16384 + 2 * AST_BYTES)   // 49152

__global__ __launch_bounds__(256, 2) void attn_mma(
    const __half* __restrict__ Q_, const __half* __restrict__ K_,
    const __half* __restrict__ V_, const int* __restrict__ lengths,
    __half* __restrict__ O_)
{
    extern __shared__ __align__(1024) char smem[];
    const int tid = threadIdx.x, wid = tid >> 5, lane = tid & 31;
    const int b = blockIdx.z, h = blockIdx.y, q0 = blockIdx.x * 128;
    const int len = lengths[b];
    uint32_t sb = smem_u32(smem);
    const size_t bh_off = ((size_t)b * H_ + h) * (S_ * DH_);

    // Q tile load (128 rows x 128B)
#pragma unroll
    for (int i = 0; i < 4; i++) {
        int idx = tid + i * 256;
        int r = idx >> 3, c = idx & 7;
        cp16(sb + AQ + SMEM_SWZ(r * 128 + c * 16), Q_ + bh_off + (size_t)(q0 + r) * DH_ + c * 8);
    }
    CP_COMMIT();

    const int jend = (len + 63) & ~63;
    const int ntile = jend >> 6;

    // prefetch KV tile 0 -> stage 0
    {
        uint32_t so = sb + AST;
#pragma unroll
        for (int i = 0; i < 2; i++) {
            int idx = tid + i * 256;
            int r = idx >> 3, c = idx & 7;
            size_t g = bh_off + (size_t)r * DH_ + c * 8;
            uint32_t sw = SMEM_SWZ(r * 128 + c * 16);
            cp16(so + AK + sw, K_ + g);
            cp16(so + AV + sw, V_ + g);
        }
        CP_COMMIT();
    }

    CP_WAIT1();
    __syncthreads();

    const int a_row = wid * 16 + (lane & 15);
    const int a_co = (lane >> 4) * 16;
    uint32_t qh[4][4];
#pragma unroll
    for (int s = 0; s < 4; s++) {
        uint32_t off = SMEM_SWZ(a_row * 128 + s * 32 + a_co);
        ldsm4(qh[s], sb + AQ + off);
    }

    float oa[8][4];
#pragma unroll
    for (int i = 0; i < 8; i++)
#pragma unroll
        for (int j = 0; j < 4; j++) oa[i][j] = 0.f;
    float m0 = -1e30f, m1 = -1e30f, l0 = 0.f, l1 = 0.f;

    const int krow = ((lane >> 4) << 3) + (lane & 7);
    const int kco  = ((lane >> 3) & 1) * 16;
    const int vrow = lane & 15;
    const int vco  = (lane >> 4) * 16;

#pragma unroll 1
    for (int t = 0; t < ntile; t++) {
        CP_WAIT0();
        __syncthreads();
        if (t + 1 < ntile) {
            uint32_t so = sb + AST + ((t + 1) & 1) * AST_BYTES;
            int j0n = (t + 1) * 64;
#pragma unroll
            for (int i = 0; i < 2; i++) {
                int idx = tid + i * 256;
                int r = idx >> 3, c = idx & 7;
                size_t g = bh_off + (size_t)(j0n + r) * DH_ + c * 8;
                uint32_t sw = SMEM_SWZ(r * 128 + c * 16);
                cp16(so + AK + sw, K_ + g);
                cp16(so + AV + sw, V_ + g);
            }
            CP_COMMIT();
        }

        const uint32_t so = sb + AST + (t & 1) * AST_BYTES;
        const int j0 = t * 64;

        // ---- S = Q @ K^T ----
        float S[8][4];
#pragma unroll
        for (int i = 0; i < 8; i++)
#pragma unroll
            for (int j = 0; j < 4; j++) S[i][j] = 0.f;
#pragma unroll
        for (int s = 0; s < 4; s++) {
            uint32_t kh4[4][4];
#pragma unroll
            for (int g = 0; g < 4; g++) {
                uint32_t off = SMEM_SWZ((g * 16 + krow) * 128 + s * 32 + kco);
                ldsm4(kh4[g], so + AK + off);
            }
#pragma unroll
            for (int g = 0; g < 4; g++) {
                mma16816(S[2 * g],     qh[s], kh4[g]);
                mma16816(S[2 * g + 1], qh[s], kh4[g] + 2);
            }
        }

        // ---- scale + mask ----
        if (j0 + 64 > len) {
            int kb0 = j0 + 2 * (lane & 3);
#pragma unroll
            for (int j = 0; j < 8; j++) {
#pragma unroll
                for (int e = 0; e < 4; e++) {
                    int kk = kb0 + 8 * j + (e & 1);
                    S[j][e] = (kk < len) ? S[j][e] * 0.125f : -1e9f;
                }
            }
        } else {
#pragma unroll
            for (int j = 0; j < 8; j++)
#pragma unroll
                for (int e = 0; e < 4; e++) S[j][e] *= 0.125f;
        }

        // ---- online softmax ----
        float mx0 = -1e30f, mx1 = -1e30f;
#pragma unroll
        for (int j = 0; j < 8; j++) {
            mx0 = fmaxf(mx0, fmaxf(S[j][0], S[j][1]));
            mx1 = fmaxf(mx1, fmaxf(S[j][2], S[j][3]));
        }
        mx0 = fmaxf(mx0, __shfl_xor_sync(0xffffffffu, mx0, 1));
        mx0 = fmaxf(mx0, __shfl_xor_sync(0xffffffffu, mx0, 2));
        mx1 = fmaxf(mx1, __shfl_xor_sync(0xffffffffu, mx1, 1));
        mx1 = fmaxf(mx1, __shfl_xor_sync(0xffffffffu, mx1, 2));
        float mn0 = fmaxf(m0, mx0), mn1 = fmaxf(m1, mx1);
        float f0 = __expf(m0 - mn0), f1 = __expf(m1 - mn1);
        l0 *= f0; l1 *= f1;
#pragma unroll
        for (int i = 0; i < 8; i++) {
            oa[i][0] *= f0; oa[i][1] *= f0; oa[i][2] *= f1; oa[i][3] *= f1;
        }
        float rs0 = 0.f, rs1 = 0.f;
#pragma unroll
        for (int j = 0; j < 8; j++) {
            S[j][0] = __expf(S[j][0] - mn0);
            S[j][1] = __expf(S[j][1] - mn0);
            S[j][2] = __expf(S[j][2] - mn1);
            S[j][3] = __expf(S[j][3] - mn1);
            rs0 += S[j][0] + S[j][1];
            rs1 += S[j][2] + S[j][3];
        }
        rs0 += __shfl_xor_sync(0xffffffffu, rs0, 1);
        rs0 += __shfl_xor_sync(0xffffffffu, rs0, 2);
        rs1 += __shfl_xor_sync(0xffffffffu, rs1, 1);
        rs1 += __shfl_xor_sync(0xffffffffu, rs1, 2);
        l0 += rs0; l1 += rs1;
        m0 = mn0; m1 = mn1;

        // ---- O += P @ V ----
#pragma unroll
        for (int s = 0; s < 4; s++) {
            uint32_t pah[4];
#pragma unroll
            for (int half = 0; half < 2; half++) {
                const float* Sf = S[2 * s + half];
                __half2 hp0 = __floats2half2_rn(Sf[0], Sf[1]);
                __half2 hp1 = __floats2half2_rn(Sf[2], Sf[3]);
                pah[2 * half]     = *(uint32_t*)&hp0;
                pah[2 * half + 1] = *(uint32_t*)&hp1;
            }
            uint32_t vh4[4][4];
#pragma unroll
            for (int g = 0; g < 4; g++) {
                uint32_t off = SMEM_SWZ((s * 16 + vrow) * 128 + g * 32 + vco);
                ldsm4t(vh4[g], so + AV + off);
            }
#pragma unroll
            for (int g = 0; g < 4; g++) {
                mma16816(oa[2 * g],     pah, vh4[g]);
                mma16816(oa[2 * g + 1], pah, vh4[g] + 2);
            }
        }
    }

    // ---- epilogue: normalize, write fp16 row-major [M][D] ----
    float il0 = 1.f / l0, il1 = 1.f / l1;
    int qrow = q0 + wid * 16 + (lane >> 2);
    size_t base0 = ((size_t)b * S_ + qrow) * D_ + h * DH_ + 2 * (lane & 3);
    size_t base1 = base0 + (size_t)8 * D_;
#pragma unroll
    for (int nf = 0; nf < 8; nf++) {
        *(__half2*)(O_ + base0 + 8 * nf) = __floats2half2_rn(oa[nf][0] * il0, oa[nf][1] * il0);
        *(__half2*)(O_ + base1 + 8 * nf) = __floats2half2_rn(oa[nf][2] * il1, oa[nf][3] * il1);
    }
}

// ---------------------------------------------------------------------------
// fp32 -> fp16 (row-major, for input v)
// ---------------------------------------------------------------------------
__global__ __launch_bounds__(256) void tofp16_kernel(
    const float4* __restrict__ x, __half2* __restrict__ o, int n4)
{
    int i = blockIdx.x * blockDim.x + threadIdx.x;
    if (i >= n4) return;
    float4 v = x[i];
    o[2 * i]     = __floats2half2_rn(v.x, v.y);
    o[2 * i + 1] = __floats2half2_rn(v.z, v.w);
}

// ---------------------------------------------------------------------------
// All 4 weights: W[K,N] fp32 -> concat W^T[4096][1024] fp16
// grid (32,32,4), block (32,8)
// ---------------------------------------------------------------------------
__global__ __launch_bounds__(256) void transpose4(
    const float* __restrict__ W0, const float* __restrict__ W1,
    const float* __restrict__ W2, const float* __restrict__ W3,
    __half* __restrict__ T_)
{
    __shared__ float t[32][33];
    const int z = blockIdx.z;
    const float* W = (z == 0) ? W0 : (z == 1) ? W1 : (z == 2) ? W2 : W3;
    const int n0 = blockIdx.x * 32, k0 = blockIdx.y * 32;
    const int tx = threadIdx.x, ty = threadIdx.y;
#pragma unroll
    for (int i = 0; i < 4; i++)
        t[ty + i * 8][tx] = W[(size_t)(k0 + ty + i * 8) * D_ + n0 + tx];
    __syncthreads();
#pragma unroll
    for (int i = 0; i < 4; i++) {
        int n = z * D_ + n0 + ty + i * 8;
        T_[(size_t)n * D_ + k0 + tx] = __float2half_rn(t[tx][ty + i * 8]);
    }
}

// ---------------------------------------------------------------------------
// Launch
// ---------------------------------------------------------------------------
extern "C" void kernel_launch(void* const* d_in, const int* in_sizes, int n_in,
                              void* d_out, int out_size)
{
    (void)in_sizes; (void)n_in; (void)out_size;
    const float* v       = (const float*)d_in[0];
    const int*   lengths = (const int*)  d_in[1];
    const float* Wq      = (const float*)d_in[2];
    const float* bq      = (const float*)d_in[3];
    const float* Wk      = (const float*)d_in[4];
    const float* bk      = (const float*)d_in[5];
    const float* Wv      = (const float*)d_in[6];
    const float* bv      = (const float*)d_in[7];
    const float* Wo      = (const float*)d_in[8];
    const float* bo      = (const float*)d_in[9];
    float* out = (float*)d_out;

    __half *xb, *wb, *qb, *kb, *vb;
    cudaGetSymbolAddress((void**)&xb, g_X);
    cudaGetSymbolAddress((void**)&wb, g_B);
    cudaGetSymbolAddress((void**)&qb, g_Q);
    cudaGetSymbolAddress((void**)&kb, g_K);
    cudaGetSymbolAddress((void**)&vb, g_V);

    cudaFuncSetAttribute(gemm_qkv, cudaFuncAttributeMaxDynamicSharedMemorySize, GEMM_SMEM);
    cudaFuncSetAttribute(gemm_out, cudaFuncAttributeMaxDynamicSharedMemorySize, GEMM_SMEM);
    cudaFuncSetAttribute(attn_mma, cudaFuncAttributeMaxDynamicSharedMemorySize, ATTN_SMEM);

    const int n4 = M_ * D_ / 4;
    dim3 gsplit((n4 + 255) / 256);
    dim3 gtr(32, 32, 4), btr(32, 8);

    transpose4<<<gtr, btr>>>(Wq, Wk, Wv, Wo, wb);
    tofp16_kernel<<<gsplit, 256>>>((const float4*)v, (__half2*)xb, n4);

    dim3 gqkv(3 * D_ / 128, M_ / 128);   // (24, 64)
    gemm_qkv<<<gqkv, 256, GEMM_SMEM>>>(xb, wb, bq, bk, bv, qb, kb, vb, lengths);

    dim3 ga(S_ / 128, H_, B_);           // (4, 16, 16)
    attn_mma<<<ga, 256, ATTN_SMEM>>>(qb, kb, vb, lengths, xb);

    dim3 go(D_ / 128, M_ / 128);         // (8, 64)
    gemm_out<<<go, 256, GEMM_SMEM>>>(xb, wb + (size_t)3 * D_ * D_, bo, out);
}

// round 13
// speedup vs baseline: 2.6740x; 1.0292x over previous
#include <cuda_runtime.h>
#include <cuda_fp16.h>
#include <cstdint>
#include <cstddef>

// Problem constants
#define B_  16
#define S_  512
#define D_  1024
#define H_  16
#define DH_ 64
#define M_  (B_ * S_)   // 8192

// Q pre-scale: 1/sqrt(64) * log2(e), folded into the Q projection epilogue so
// attention can use raw ex2 (no per-element scale multiply, no expf's hidden mul)
#define QSCALE 0.18033688011112042f

// ---------------------------------------------------------------------------
// Scratch (static device globals), all single fp16
// ---------------------------------------------------------------------------
__device__ __align__(128) __half g_X[M_ * D_];      // v (fp16), later attn out (row-major)
__device__ __align__(128) __half g_B[4 * D_ * D_];  // concat W^T [4096][1024] (Q,K,V,O)
__device__ __align__(128) __half g_Q[M_ * D_];      // head-major [b,h,s,dh]
__device__ __align__(128) __half g_K[M_ * D_];
__device__ __align__(128) __half g_V[M_ * D_];

// ---------------------------------------------------------------------------
// PTX helpers (sm_80+ only; compute_103 lowering rejects sm_103a-only features)
// ---------------------------------------------------------------------------
__device__ __forceinline__ uint32_t smem_u32(const void* p) {
    uint32_t a;
    asm("{ .reg .u64 t; cvta.to.shared.u64 t, %1; cvt.u32.u64 %0, t; }" : "=r"(a) : "l"(p));
    return a;
}
__device__ __forceinline__ void cp16(uint32_t saddr, const void* gaddr) {
    asm volatile("cp.async.cg.shared.global [%0], [%1], 16;" :: "r"(saddr), "l"(gaddr) : "memory");
}
#define CP_COMMIT() asm volatile("cp.async.commit_group;" ::: "memory")
#define CP_WAIT0()  asm volatile("cp.async.wait_group 0;" ::: "memory")
#define CP_WAIT1()  asm volatile("cp.async.wait_group 1;" ::: "memory")
#define CP_WAIT2()  asm volatile("cp.async.wait_group 2;" ::: "memory")

__device__ __forceinline__ void ldsm4(uint32_t* r, uint32_t a) {
    asm volatile("ldmatrix.sync.aligned.m8n8.x4.shared.b16 {%0,%1,%2,%3}, [%4];"
                 : "=r"(r[0]), "=r"(r[1]), "=r"(r[2]), "=r"(r[3]) : "r"(a));
}
__device__ __forceinline__ void ldsm4t(uint32_t* r, uint32_t a) {
    asm volatile("ldmatrix.sync.aligned.m8n8.x4.trans.shared.b16 {%0,%1,%2,%3}, [%4];"
                 : "=r"(r[0]), "=r"(r[1]), "=r"(r[2]), "=r"(r[3]) : "r"(a));
}
// fp16 HMMA, fp32 accumulate
__device__ __forceinline__ void mma16816(float* c, const uint32_t* a, const uint32_t* b) {
    asm volatile(
        "mma.sync.aligned.m16n8k16.row.col.f32.f16.f16.f32 "
        "{%0,%1,%2,%3}, {%4,%5,%6,%7}, {%8,%9}, {%0,%1,%2,%3};"
        : "+f"(c[0]), "+f"(c[1]), "+f"(c[2]), "+f"(c[3])
        : "r"(a[0]), "r"(a[1]), "r"(a[2]), "r"(a[3]), "r"(b[0]), "r"(b[1]));
}
__device__ __forceinline__ float ex2(float x) {
    float r;
    asm("ex2.approx.f32 %0, %1;" : "=f"(r) : "f"(x));
    return r;
}

#define SMEM_SWZ(o)   ((o) ^ (((o) >> 3) & 0x70))   // 128B rows
#define SMEM_SWZ32(o) ((o) ^ (((o) >> 3) & 0x30))   // 64B rows (BK=32)

// ---------------------------------------------------------------------------
// GEMM: C = A @ B^T (+bias), single fp16, fp32 accum.
// CTA tile 128x128, BK=32, 3-stage cp.async, 8 warps 2x4, 2 CTAs/SM.
// ---------------------------------------------------------------------------
#define T_A 0
#define T_B 8192
#define STAGE_BYTES 16384
#define GEMM_SMEM (3 * STAGE_BYTES)   // 49152

__device__ __forceinline__ void load_tile32(uint32_t sdst, const __half* g,
                                            int row0, int kc, int tid) {
#pragma unroll
    for (int i = 0; i < 2; i++) {
        int idx = tid + i * 256;          // 512 transfers of 16B
        int r = idx >> 2, c = idx & 3;    // 128 rows x 4 chunks
        const __half* gp = g + (size_t)(row0 + r) * D_ + kc * 32 + c * 8;
        cp16(sdst + SMEM_SWZ32(r * 64 + c * 16), gp);
    }
}

__device__ __forceinline__ void gemm_mainloop(
    uint32_t sb, const __half* A, const __half* Bp,
    int m0, int tid, int wid, int lane, float acc[4][4][4])
{
    const int wm = (wid >> 2) * 64;
    const int wn = (wid & 3) * 32;
    const int a_row = wm + (lane & 15);
    const int a_coff = (lane >> 4) * 16;
    const int b_row = wn + ((lane >> 4) << 3) + (lane & 7);
    const int b_coff = ((lane >> 3) & 1) * 16;

#pragma unroll
    for (int p = 0; p < 2; p++) {
        uint32_t so = sb + p * STAGE_BYTES;
        load_tile32(so + T_A, A, m0, p, tid);
        load_tile32(so + T_B, Bp, 0, p, tid);
        CP_COMMIT();
    }

    int stage = 0, nstage = 2;
#pragma unroll 1
    for (int c = 0; c < 32; c++) {
        if (c + 2 < 32) {
            uint32_t so = sb + nstage * STAGE_BYTES;
            load_tile32(so + T_A, A, m0, c + 2, tid);
            load_tile32(so + T_B, Bp, 0, c + 2, tid);
            CP_COMMIT();
            CP_WAIT2();
        } else if (c + 1 < 32) {
            CP_WAIT1();
        } else {
            CP_WAIT0();
        }
        __syncthreads();

        const uint32_t so = sb + stage * STAGE_BYTES;
#pragma unroll
        for (int ks = 0; ks < 2; ks++) {
            const int kb = ks * 32;
            uint32_t ah[4][4], bh[2][4];
#pragma unroll
            for (int mt = 0; mt < 4; mt++) {
                uint32_t off = SMEM_SWZ32((a_row + mt * 16) * 64 + kb + a_coff);
                ldsm4(ah[mt], so + T_A + off);
            }
#pragma unroll
            for (int nt2 = 0; nt2 < 2; nt2++) {
                uint32_t off = SMEM_SWZ32((b_row + nt2 * 16) * 64 + kb + b_coff);
                ldsm4(bh[nt2], so + T_B + off);
            }
#pragma unroll
            for (int mt = 0; mt < 4; mt++)
#pragma unroll
                for (int nt = 0; nt < 4; nt++)
                    mma16816(acc[mt][nt], ah[mt], &bh[nt >> 1][(nt & 1) * 2]);
        }
        __syncthreads();
        stage = (stage + 1) == 3 ? 0 : stage + 1;
        nstage = (nstage + 1) == 3 ? 0 : nstage + 1;
    }
}

// ---------------------------------------------------------------------------
// Fused QKV projection GEMM: grid (24, 64); proj = n0>>10. K/V skip by length.
// Q output pre-scaled by QSCALE (softmax exp2 fold). All outputs fp16 head-major.
// ---------------------------------------------------------------------------
__global__ __launch_bounds__(256, 2) void gemm_qkv(
    const __half* __restrict__ A, const __half* __restrict__ Bc,
    const float* __restrict__ bq, const float* __restrict__ bk, const float* __restrict__ bv,
    __half* __restrict__ qo, __half* __restrict__ ko, __half* __restrict__ vo,
    const int* __restrict__ lengths)
{
    extern __shared__ __align__(1024) char smem[];
    const int tid  = threadIdx.x;
    const int wid  = tid >> 5, lane = tid & 31;
    const int m0   = blockIdx.y * 128;
    const int n0   = blockIdx.x * 128;
    const int proj = n0 >> 10;

    if (proj != 0) {
        int len = lengths[m0 >> 9];
        if ((m0 & 511) >= ((len + 63) & ~63)) return;
    }

    const float* bias = (proj == 0) ? bq : (proj == 1) ? bk : bv;
    __half* Co = (proj == 0) ? qo : (proj == 1) ? ko : vo;
    const float sc = (proj == 0) ? QSCALE : 1.0f;

    uint32_t sb = smem_u32(smem);
    float acc[4][4][4];
#pragma unroll
    for (int i = 0; i < 4; i++)
#pragma unroll
        for (int j = 0; j < 4; j++)
#pragma unroll
            for (int k = 0; k < 4; k++) acc[i][j][k] = 0.f;

    gemm_mainloop(sb, A, Bc + (size_t)n0 * D_, m0, tid, wid, lane, acc);

    const int wm = (wid >> 2) * 64;
    const int wn = (wid & 3) * 32;
    const int er = lane >> 2;
    const int ec = (lane & 3) * 2;
#pragma unroll
    for (int mt = 0; mt < 4; mt++) {
#pragma unroll
        for (int nt = 0; nt < 4; nt++) {
            int row = m0 + wm + mt * 16 + er;
            int lc  = (n0 & 1023) + wn + nt * 8 + ec;
            float b0 = bias[lc], b1 = bias[lc + 1];
            int bb = row >> 9, ss = row & 511, hh = lc >> 6, dd = lc & 63;
            size_t base = (((size_t)bb * H_ + hh) * S_ + ss) * DH_ + dd;
            *(__half2*)(Co + base) =
                __floats2half2_rn((acc[mt][nt][0] + b0) * sc, (acc[mt][nt][1] + b1) * sc);
            *(__half2*)(Co + base + 8 * DH_) =
                __floats2half2_rn((acc[mt][nt][2] + b0) * sc, (acc[mt][nt][3] + b1) * sc);
        }
    }
}

// ---------------------------------------------------------------------------
// Output projection GEMM: out = A @ Wo^T + bo (fp32 row-major), grid (8, 64)
// ---------------------------------------------------------------------------
__global__ __launch_bounds__(256, 2) void gemm_out(
    const __half* __restrict__ A, const __half* __restrict__ Bc,
    const float* __restrict__ bias, float* __restrict__ C)
{
    extern __shared__ __align__(1024) char smem[];
    const int tid  = threadIdx.x;
    const int wid  = tid >> 5, lane = tid & 31;
    const int m0   = blockIdx.y * 128;
    const int n0   = blockIdx.x * 128;

    uint32_t sb = smem_u32(smem);
    float acc[4][4][4];
#pragma unroll
    for (int i = 0; i < 4; i++)
#pragma unroll
        for (int j = 0; j < 4; j++)
#pragma unroll
            for (int k = 0; k < 4; k++) acc[i][j][k] = 0.f;

    gemm_mainloop(sb, A, Bc + (size_t)n0 * D_, m0, tid, wid, lane, acc);

    const int wm = (wid >> 2) * 64;
    const int wn = (wid & 3) * 32;
    const int er = lane >> 2;
    const int ec = (lane & 3) * 2;
#pragma unroll
    for (int mt = 0; mt < 4; mt++) {
#pragma unroll
        for (int nt = 0; nt < 4; nt++) {
            int row = m0 + wm + mt * 16 + er;
            int col = n0 + wn + nt * 8 + ec;
            float b0 = bias[col], b1 = bias[col + 1];
            float2 p0 = make_float2(acc[mt][nt][0] + b0, acc[mt][nt][1] + b1);
            float2 p1 = make_float2(acc[mt][nt][2] + b0, acc[mt][nt][3] + b1);
            *(float2*)(C + (size_t)row * D_ + col) = p0;
            *(float2*)(C + (size_t)(row + 8) * D_ + col) = p1;
        }
    }
}

// ---------------------------------------------------------------------------
// HMMA flash attention, fp16 operands, fp32 accum, exp2-domain softmax
// (Q pre-scaled by QSCALE). 64-key tiles, 2-stage. Writes fp16 row-major.
// ---------------------------------------------------------------------------
#define AQ   0
#define AST  16384
#define AK   0
#define AV   8192
#define AST_BYTES 16384
#define ATTN_SMEM (16384 + 2 * AST_BYTES)   // 49152

__global__ __launch_bounds__(256, 2) void attn_mma(
    const __half* __restrict__ Q_, const __half* __restrict__ K_,
    const __half* __restrict__ V_, const int* __restrict__ lengths,
    __half* __restrict__ O_)
{
    extern __shared__ __align__(1024) char smem[];
    const int tid = threadIdx.x, wid = tid >> 5, lane = tid & 31;
    const int b = blockIdx.z, h = blockIdx.y, q0 = blockIdx.x * 128;
    const int len = lengths[b];
    uint32_t sb = smem_u32(smem);
    const size_t bh_off = ((size_t)b * H_ + h) * (S_ * DH_);

    // Q tile load (128 rows x 128B)
#pragma unroll
    for (int i = 0; i < 4; i++) {
        int idx = tid + i * 256;
        int r = idx >> 3, c = idx & 7;
        cp16(sb + AQ + SMEM_SWZ(r * 128 + c * 16), Q_ + bh_off + (size_t)(q0 + r) * DH_ + c * 8);
    }
    CP_COMMIT();

    const int jend = (len + 63) & ~63;
    const int ntile = jend >> 6;

    // prefetch KV tile 0 -> stage 0
    {
        uint32_t so = sb + AST;
#pragma unroll
        for (int i = 0; i < 2; i++) {
            int idx = tid + i * 256;
            int r = idx >> 3, c = idx & 7;
            size_t g = bh_off + (size_t)r * DH_ + c * 8;
            uint32_t sw = SMEM_SWZ(r * 128 + c * 16);
            cp16(so + AK + sw, K_ + g);
            cp16(so + AV + sw, V_ + g);
        }
        CP_COMMIT();
    }

    CP_WAIT1();
    __syncthreads();

    const int a_row = wid * 16 + (lane & 15);
    const int a_co = (lane >> 4) * 16;
    uint32_t qh[4][4];
#pragma unroll
    for (int s = 0; s < 4; s++) {
        uint32_t off = SMEM_SWZ(a_row * 128 + s * 32 + a_co);
        ldsm4(qh[s], sb + AQ + off);
    }

    float oa[8][4];
#pragma unroll
    for (int i = 0; i < 8; i++)
#pragma unroll
        for (int j = 0; j < 4; j++) oa[i][j] = 0.f;
    float m0 = -1e30f, m1 = -1e30f, l0 = 0.f, l1 = 0.f;

    const int krow = ((lane >> 4) << 3) + (lane & 7);
    const int kco  = ((lane >> 3) & 1) * 16;
    const int vrow = lane & 15;
    const int vco  = (lane >> 4) * 16;

#pragma unroll 1
    for (int t = 0; t < ntile; t++) {
        CP_WAIT0();
        __syncthreads();
        if (t + 1 < ntile) {
            uint32_t so = sb + AST + ((t + 1) & 1) * AST_BYTES;
            int j0n = (t + 1) * 64;
#pragma unroll
            for (int i = 0; i < 2; i++) {
                int idx = tid + i * 256;
                int r = idx >> 3, c = idx & 7;
                size_t g = bh_off + (size_t)(j0n + r) * DH_ + c * 8;
                uint32_t sw = SMEM_SWZ(r * 128 + c * 16);
                cp16(so + AK + sw, K_ + g);
                cp16(so + AV + sw, V_ + g);
            }
            CP_COMMIT();
        }

        const uint32_t so = sb + AST + (t & 1) * AST_BYTES;
        const int j0 = t * 64;

        // ---- S = Q @ K^T (already in log2 domain via Q pre-scale) ----
        float S[8][4];
#pragma unroll
        for (int i = 0; i < 8; i++)
#pragma unroll
            for (int j = 0; j < 4; j++) S[i][j] = 0.f;
#pragma unroll
        for (int s = 0; s < 4; s++) {
            uint32_t kh4[4][4];
#pragma unroll
            for (int g = 0; g < 4; g++) {
                uint32_t off = SMEM_SWZ((g * 16 + krow) * 128 + s * 32 + kco);
                ldsm4(kh4[g], so + AK + off);
            }
#pragma unroll
            for (int g = 0; g < 4; g++) {
                mma16816(S[2 * g],     qh[s], kh4[g]);
                mma16816(S[2 * g + 1], qh[s], kh4[g] + 2);
            }
        }

        // ---- mask (partial tiles only; no scale needed) ----
        if (j0 + 64 > len) {
            int kb0 = j0 + 2 * (lane & 3);
#pragma unroll
            for (int j = 0; j < 8; j++) {
#pragma unroll
                for (int e = 0; e < 4; e++) {
                    int kk = kb0 + 8 * j + (e & 1);
                    if (kk >= len) S[j][e] = -1e9f;
                }
            }
        }

        // ---- online softmax (base-2) ----
        float mx0 = -1e30f, mx1 = -1e30f;
#pragma unroll
        for (int j = 0; j < 8; j++) {
            mx0 = fmaxf(mx0, fmaxf(S[j][0], S[j][1]));
            mx1 = fmaxf(mx1, fmaxf(S[j][2], S[j][3]));
        }
        mx0 = fmaxf(mx0, __shfl_xor_sync(0xffffffffu, mx0, 1));
        mx0 = fmaxf(mx0, __shfl_xor_sync(0xffffffffu, mx0, 2));
        mx1 = fmaxf(mx1, __shfl_xor_sync(0xffffffffu, mx1, 1));
        mx1 = fmaxf(mx1, __shfl_xor_sync(0xffffffffu, mx1, 2));
        float mn0 = fmaxf(m0, mx0), mn1 = fmaxf(m1, mx1);
        float f0 = ex2(m0 - mn0), f1 = ex2(m1 - mn1);
        l0 *= f0; l1 *= f1;
#pragma unroll
        for (int i = 0; i < 8; i++) {
            oa[i][0] *= f0; oa[i][1] *= f0; oa[i][2] *= f1; oa[i][3] *= f1;
        }
        float rs0 = 0.f, rs1 = 0.f;
#pragma unroll
        for (int j = 0; j < 8; j++) {
            S[j][0] = ex2(S[j][0] - mn0);
            S[j][1] = ex2(S[j][1] - mn0);
            S[j][2] = ex2(S[j][2] - mn1);
            S[j][3] = ex2(S[j][3] - mn1);
            rs0 += S[j][0] + S[j][1];
            rs1 += S[j][2] + S[j][3];
        }
        rs0 += __shfl_xor_sync(0xffffffffu, rs0, 1);
        rs0 += __shfl_xor_sync(0xffffffffu, rs0, 2);
        rs1 += __shfl_xor_sync(0xffffffffu, rs1, 1);
        rs1 += __shfl_xor_sync(0xffffffffu, rs1, 2);
        l0 += rs0; l1 += rs1;
        m0 = mn0; m1 = mn1;

        // ---- O += P @ V ----
#pragma unroll
        for (int s = 0; s < 4; s++) {
            uint32_t pah[4];
#pragma unroll
            for (int half = 0; half < 2; half++) {
                const float* Sf = S[2 * s + half];
                __half2 hp0 = __floats2half2_rn(Sf[0], Sf[1]);
                __half2 hp1 = __floats2half2_rn(Sf[2], Sf[3]);
                pah[2 * half]     = *(uint32_t*)&hp0;
                pah[2 * half + 1] = *(uint32_t*)&hp1;
            }
            uint32_t vh4[4][4];
#pragma unroll
            for (int g = 0; g < 4; g++) {
                uint32_t off = SMEM_SWZ((s * 16 + vrow) * 128 + g * 32 + vco);
                ldsm4t(vh4[g], so + AV + off);
            }
#pragma unroll
            for (int g = 0; g < 4; g++) {
                mma16816(oa[2 * g],     pah, vh4[g]);
                mma16816(oa[2 * g + 1], pah, vh4[g] + 2);
            }
        }
    }

    // ---- epilogue: normalize, write fp16 row-major [M][D] ----
    float il0 = 1.f / l0, il1 = 1.f / l1;
    int qrow = q0 + wid * 16 + (lane >> 2);
    size_t base0 = ((size_t)b * S_ + qrow) * D_ + h * DH_ + 2 * (lane & 3);
    size_t base1 = base0 + (size_t)8 * D_;
#pragma unroll
    for (int nf = 0; nf < 8; nf++) {
        *(__half2*)(O_ + base0 + 8 * nf) = __floats2half2_rn(oa[nf][0] * il0, oa[nf][1] * il0);
        *(__half2*)(O_ + base1 + 8 * nf) = __floats2half2_rn(oa[nf][2] * il1, oa[nf][3] * il1);
    }
}

// ---------------------------------------------------------------------------
// Combined prep: z 0..3 = weight transpose (W[K,N] fp32 -> concat W^T fp16),
// z 4..11 = v fp32 -> fp16. grid (32,32,12), block (32,8) = 256 threads.
// ---------------------------------------------------------------------------
__global__ __launch_bounds__(256) void prep_kernel(
    const float* __restrict__ W0, const float* __restrict__ W1,
    const float* __restrict__ W2, const float* __restrict__ W3,
    __half* __restrict__ T_,
    const float4* __restrict__ x, __half2* __restrict__ xo)
{
    const int z = blockIdx.z;
    if (z < 4) {
        __shared__ float t[32][33];
        const float* W = (z == 0) ? W0 : (z == 1) ? W1 : (z == 2) ? W2 : W3;
        const int n0 = blockIdx.x * 32, k0 = blockIdx.y * 32;
        const int tx = threadIdx.x, ty = threadIdx.y;
#pragma unroll
        for (int i = 0; i < 4; i++)
            t[ty + i * 8][tx] = W[(size_t)(k0 + ty + i * 8) * D_ + n0 + tx];
        __syncthreads();
#pragma unroll
        for (int i = 0; i < 4; i++) {
            int n = z * D_ + n0 + ty + i * 8;
            T_[(size_t)n * D_ + k0 + tx] = __float2half_rn(t[tx][ty + i * 8]);
        }
    } else {
        int tid = threadIdx.y * 32 + threadIdx.x;
        int blk = (z - 4) * 1024 + blockIdx.y * 32 + blockIdx.x;
        int i = blk * 256 + tid;           // < 8192*256 = 2M float4 exactly
        float4 v = x[i];
        xo[2 * i]     = __floats2half2_rn(v.x, v.y);
        xo[2 * i + 1] = __floats2half2_rn(v.z, v.w);
    }
}

// ---------------------------------------------------------------------------
// Launch
// ---------------------------------------------------------------------------
extern "C" void kernel_launch(void* const* d_in, const int* in_sizes, int n_in,
                              void* d_out, int out_size)
{
    (void)in_sizes; (void)n_in; (void)out_size;
    const float* v       = (const float*)d_in[0];
    const int*   lengths = (const int*)  d_in[1];
    const float* Wq      = (const float*)d_in[2];
    const float* bq      = (const float*)d_in[3];
    const float* Wk      = (const float*)d_in[4];
    const float* bk      = (const float*)d_in[5];
    const float* Wv      = (const float*)d_in[6];
    const float* bv      = (const float*)d_in[7];
    const float* Wo      = (const float*)d_in[8];
    const float* bo      = (const float*)d_in[9];
    float* out = (float*)d_out;

    __half *xb, *wb, *qb, *kb, *vb;
    cudaGetSymbolAddress((void**)&xb, g_X);
    cudaGetSymbolAddress((void**)&wb, g_B);
    cudaGetSymbolAddress((void**)&qb, g_Q);
    cudaGetSymbolAddress((void**)&kb, g_K);
    cudaGetSymbolAddress((void**)&vb, g_V);

    cudaFuncSetAttribute(gemm_qkv, cudaFuncAttributeMaxDynamicSharedMemorySize, GEMM_SMEM);
    cudaFuncSetAttribute(gemm_out, cudaFuncAttributeMaxDynamicSharedMemorySize, GEMM_SMEM);
    cudaFuncSetAttribute(attn_mma, cudaFuncAttributeMaxDynamicSharedMemorySize, ATTN_SMEM);

    dim3 gprep(32, 32, 12), bprep(32, 8);
    prep_kernel<<<gprep, bprep>>>(Wq, Wk, Wv, Wo, wb, (const float4*)v, (__half2*)xb);

    dim3 gqkv(3 * D_ / 128, M_ / 128);   // (24, 64)
    gemm_qkv<<<gqkv, 256, GEMM_SMEM>>>(xb, wb, bq, bk, bv, qb, kb, vb, lengths);

    dim3 ga(S_ / 128, H_, B_);           // (4, 16, 16)
    attn_mma<<<ga, 256, ATTN_SMEM>>>(qb, kb, vb, lengths, xb);

    dim3 go(D_ / 128, M_ / 128);         // (8, 64)
    gemm_out<<<go, 256, GEMM_SMEM>>>(xb, wb + (size_t)3 * D_ * D_, bo, out);
}

// round 14
// speedup vs baseline: 2.9637x; 1.1083x over previous
#include <cuda_runtime.h>
#include <cuda_fp16.h>
#include <cstdint>
#include <cstddef>

// Problem constants
#define B_  16
#define S_  512
#define D_  1024
#define H_  16
#define DH_ 64
#define M_  (B_ * S_)   // 8192

// Q pre-scale: 1/sqrt(64) * log2(e) — folded into Q projection epilogue
#define QSCALE 0.18033688011112042f

// ---------------------------------------------------------------------------
// Scratch (static device globals), all single fp16
// ---------------------------------------------------------------------------
__device__ __align__(128) __half g_X[M_ * D_];      // v (fp16), later attn out (row-major)
__device__ __align__(128) __half g_B[4 * D_ * D_];  // concat W^T [4096][1024] (Q,K,V,O)
__device__ __align__(128) __half g_Q[M_ * D_];      // head-major [b,h,s,dh]
__device__ __align__(128) __half g_K[M_ * D_];
__device__ __align__(128) __half g_V[M_ * D_];

// ---------------------------------------------------------------------------
// PTX helpers (sm_80+ only; compute_103 lowering rejects sm_103a-only features)
// ---------------------------------------------------------------------------
__device__ __forceinline__ uint32_t smem_u32(const void* p) {
    uint32_t a;
    asm("{ .reg .u64 t; cvta.to.shared.u64 t, %1; cvt.u32.u64 %0, t; }" : "=r"(a) : "l"(p));
    return a;
}
__device__ __forceinline__ void cp16(uint32_t saddr, const void* gaddr) {
    asm volatile("cp.async.cg.shared.global [%0], [%1], 16;" :: "r"(saddr), "l"(gaddr) : "memory");
}
#define CP_COMMIT() asm volatile("cp.async.commit_group;" ::: "memory")
#define CP_WAIT0()  asm volatile("cp.async.wait_group 0;" ::: "memory")
#define CP_WAIT1()  asm volatile("cp.async.wait_group 1;" ::: "memory")
#define CP_WAIT2()  asm volatile("cp.async.wait_group 2;" ::: "memory")

__device__ __forceinline__ void ldsm4(uint32_t* r, uint32_t a) {
    asm volatile("ldmatrix.sync.aligned.m8n8.x4.shared.b16 {%0,%1,%2,%3}, [%4];"
                 : "=r"(r[0]), "=r"(r[1]), "=r"(r[2]), "=r"(r[3]) : "r"(a));
}
__device__ __forceinline__ void ldsm4t(uint32_t* r, uint32_t a) {
    asm volatile("ldmatrix.sync.aligned.m8n8.x4.trans.shared.b16 {%0,%1,%2,%3}, [%4];"
                 : "=r"(r[0]), "=r"(r[1]), "=r"(r[2]), "=r"(r[3]) : "r"(a));
}
// fp16 HMMA, fp32 accumulate
__device__ __forceinline__ void mma16816(float* c, const uint32_t* a, const uint32_t* b) {
    asm volatile(
        "mma.sync.aligned.m16n8k16.row.col.f32.f16.f16.f32 "
        "{%0,%1,%2,%3}, {%4,%5,%6,%7}, {%8,%9}, {%0,%1,%2,%3};"
        : "+f"(c[0]), "+f"(c[1]), "+f"(c[2]), "+f"(c[3])
        : "r"(a[0]), "r"(a[1]), "r"(a[2]), "r"(a[3]), "r"(b[0]), "r"(b[1]));
}
__device__ __forceinline__ float ex2(float x) {
    float r;
    asm("ex2.approx.f32 %0, %1;" : "=f"(r) : "f"(x));
    return r;
}

#define SMEM_SWZ(o)   ((o) ^ (((o) >> 3) & 0x70))   // 128B rows

// ---------------------------------------------------------------------------
// GEMM: C = A @ B^T (+bias), single fp16, fp32 accum.
// CTA tile 128x128, BK=64 (fewer barriers/iter now that MMA work is 1 term),
// 3-stage cp.async, 8 warps 2x4, 2 CTAs/SM (96KB smem each).
// ---------------------------------------------------------------------------
#define T_A 0
#define T_B 16384
#define STAGE_BYTES 32768
#define GEMM_SMEM (3 * STAGE_BYTES)   // 98304

__device__ __forceinline__ void load_tile64(uint32_t sdst, const __half* g,
                                            int row0, int kc, int tid) {
#pragma unroll
    for (int i = 0; i < 4; i++) {
        int idx = tid + i * 256;          // 1024 transfers of 16B
        int r = idx >> 3, c = idx & 7;    // 128 rows x 8 chunks
        const __half* gp = g + (size_t)(row0 + r) * D_ + kc * 64 + c * 8;
        cp16(sdst + SMEM_SWZ(r * 128 + c * 16), gp);
    }
}

__device__ __forceinline__ void gemm_mainloop(
    uint32_t sb, const __half* A, const __half* Bp,
    int m0, int tid, int wid, int lane, float acc[4][4][4])
{
    const int wm = (wid >> 2) * 64;
    const int wn = (wid & 3) * 32;
    const int a_row = wm + (lane & 15);
    const int a_coff = (lane >> 4) * 16;
    const int b_row = wn + ((lane >> 4) << 3) + (lane & 7);
    const int b_coff = ((lane >> 3) & 1) * 16;

#pragma unroll
    for (int p = 0; p < 2; p++) {
        uint32_t so = sb + p * STAGE_BYTES;
        load_tile64(so + T_A, A, m0, p, tid);
        load_tile64(so + T_B, Bp, 0, p, tid);
        CP_COMMIT();
    }

    int stage = 0, nstage = 2;
#pragma unroll 1
    for (int c = 0; c < 16; c++) {
        if (c + 2 < 16) {
            uint32_t so = sb + nstage * STAGE_BYTES;
            load_tile64(so + T_A, A, m0, c + 2, tid);
            load_tile64(so + T_B, Bp, 0, c + 2, tid);
            CP_COMMIT();
            CP_WAIT2();
        } else if (c + 1 < 16) {
            CP_WAIT1();
        } else {
            CP_WAIT0();
        }
        __syncthreads();

        const uint32_t so = sb + stage * STAGE_BYTES;
#pragma unroll
        for (int ks = 0; ks < 4; ks++) {
            const int kb = ks * 32;
            uint32_t ah[4][4], bh[2][4];
#pragma unroll
            for (int mt = 0; mt < 4; mt++) {
                uint32_t off = SMEM_SWZ((a_row + mt * 16) * 128 + kb + a_coff);
                ldsm4(ah[mt], so + T_A + off);
            }
#pragma unroll
            for (int nt2 = 0; nt2 < 2; nt2++) {
                uint32_t off = SMEM_SWZ((b_row + nt2 * 16) * 128 + kb + b_coff);
                ldsm4(bh[nt2], so + T_B + off);
            }
#pragma unroll
            for (int mt = 0; mt < 4; mt++)
#pragma unroll
                for (int nt = 0; nt < 4; nt++)
                    mma16816(acc[mt][nt], ah[mt], &bh[nt >> 1][(nt & 1) * 2]);
        }
        __syncthreads();
        stage = (stage + 1) == 3 ? 0 : stage + 1;
        nstage = (nstage + 1) == 3 ? 0 : nstage + 1;
    }
}

// ---------------------------------------------------------------------------
// Fused QKV projection GEMM: grid (24, 64); proj = n0>>10. K/V skip by length.
// Q output pre-scaled by QSCALE. All outputs fp16 head-major [b,h,s,dh].
// ---------------------------------------------------------------------------
__global__ __launch_bounds__(256, 2) void gemm_qkv(
    const __half* __restrict__ A, const __half* __restrict__ Bc,
    const float* __restrict__ bq, const float* __restrict__ bk, const float* __restrict__ bv,
    __half* __restrict__ qo, __half* __restrict__ ko, __half* __restrict__ vo,
    const int* __restrict__ lengths)
{
    extern __shared__ __align__(1024) char smem[];
    const int tid  = threadIdx.x;
    const int wid  = tid >> 5, lane = tid & 31;
    const int m0   = blockIdx.y * 128;
    const int n0   = blockIdx.x * 128;
    const int proj = n0 >> 10;

    if (proj != 0) {
        int len = lengths[m0 >> 9];
        if ((m0 & 511) >= ((len + 63) & ~63)) return;
    }

    const float* bias = (proj == 0) ? bq : (proj == 1) ? bk : bv;
    __half* Co = (proj == 0) ? qo : (proj == 1) ? ko : vo;
    const float sc = (proj == 0) ? QSCALE : 1.0f;

    uint32_t sb = smem_u32(smem);
    float acc[4][4][4];
#pragma unroll
    for (int i = 0; i < 4; i++)
#pragma unroll
        for (int j = 0; j < 4; j++)
#pragma unroll
            for (int k = 0; k < 4; k++) acc[i][j][k] = 0.f;

    gemm_mainloop(sb, A, Bc + (size_t)n0 * D_, m0, tid, wid, lane, acc);

    const int wm = (wid >> 2) * 64;
    const int wn = (wid & 3) * 32;
    const int er = lane >> 2;
    const int ec = (lane & 3) * 2;
#pragma unroll
    for (int mt = 0; mt < 4; mt++) {
#pragma unroll
        for (int nt = 0; nt < 4; nt++) {
            int row = m0 + wm + mt * 16 + er;
            int lc  = (n0 & 1023) + wn + nt * 8 + ec;
            float b0 = bias[lc], b1 = bias[lc + 1];
            int bb = row >> 9, ss = row & 511, hh = lc >> 6, dd = lc & 63;
            size_t base = (((size_t)bb * H_ + hh) * S_ + ss) * DH_ + dd;
            *(__half2*)(Co + base) =
                __floats2half2_rn((acc[mt][nt][0] + b0) * sc, (acc[mt][nt][1] + b1) * sc);
            *(__half2*)(Co + base + 8 * DH_) =
                __floats2half2_rn((acc[mt][nt][2] + b0) * sc, (acc[mt][nt][3] + b1) * sc);
        }
    }
}

// ---------------------------------------------------------------------------
// Output projection GEMM: out = A @ Wo^T + bo (fp32 row-major), grid (8, 64)
// ---------------------------------------------------------------------------
__global__ __launch_bounds__(256, 2) void gemm_out(
    const __half* __restrict__ A, const __half* __restrict__ Bc,
    const float* __restrict__ bias, float* __restrict__ C)
{
    extern __shared__ __align__(1024) char smem[];
    const int tid  = threadIdx.x;
    const int wid  = tid >> 5, lane = tid & 31;
    const int m0   = blockIdx.y * 128;
    const int n0   = blockIdx.x * 128;

    uint32_t sb = smem_u32(smem);
    float acc[4][4][4];
#pragma unroll
    for (int i = 0; i < 4; i++)
#pragma unroll
        for (int j = 0; j < 4; j++)
#pragma unroll
            for (int k = 0; k < 4; k++) acc[i][j][k] = 0.f;

    gemm_mainloop(sb, A, Bc + (size_t)n0 * D_, m0, tid, wid, lane, acc);

    const int wm = (wid >> 2) * 64;
    const int wn = (wid & 3) * 32;
    const int er = lane >> 2;
    const int ec = (lane & 3) * 2;
#pragma unroll
    for (int mt = 0; mt < 4; mt++) {
#pragma unroll
        for (int nt = 0; nt < 4; nt++) {
            int row = m0 + wm + mt * 16 + er;
            int col = n0 + wn + nt * 8 + ec;
            float b0 = bias[col], b1 = bias[col + 1];
            float2 p0 = make_float2(acc[mt][nt][0] + b0, acc[mt][nt][1] + b1);
            float2 p1 = make_float2(acc[mt][nt][2] + b0, acc[mt][nt][3] + b1);
            *(float2*)(C + (size_t)row * D_ + col) = p0;
            *(float2*)(C + (size_t)(row + 8) * D_ + col) = p1;
        }
    }
}

// ---------------------------------------------------------------------------
// HMMA flash attention, fp16 operands, fp32 accum, exp2-domain softmax
// (Q pre-scaled by QSCALE). 64-key tiles, 2-stage. Writes fp16 row-major.
// ---------------------------------------------------------------------------
#define AQ   0
#define AST  16384
#define AK   0
#define AV   8192
#define AST_BYTES 16384
#define ATTN_SMEM (16384 + 2 * AST_BYTES)   // 49152

__global__ __launch_bounds__(256, 2) void attn_mma(
    const __half* __restrict__ Q_, const __half* __restrict__ K_,
    const __half* __restrict__ V_, const int* __restrict__ lengths,
    __half* __restrict__ O_)
{
    extern __shared__ __align__(1024) char smem[];
    const int tid = threadIdx.x, wid = tid >> 5, lane = tid & 31;
    const int b = blockIdx.z, h = blockIdx.y, q0 = blockIdx.x * 128;
    const int len = lengths[b];
    uint32_t sb = smem_u32(smem);
    const size_t bh_off = ((size_t)b * H_ + h) * (S_ * DH_);

    // Q tile load (128 rows x 128B)
#pragma unroll
    for (int i = 0; i < 4; i++) {
        int idx = tid + i * 256;
        int r = idx >> 3, c = idx & 7;
        cp16(sb + AQ + SMEM_SWZ(r * 128 + c * 16), Q_ + bh_off + (size_t)(q0 + r) * DH_ + c * 8);
    }
    CP_COMMIT();

    const int jend = (len + 63) & ~63;
    const int ntile = jend >> 6;

    // prefetch KV tile 0 -> stage 0
    {
        uint32_t so = sb + AST;
#pragma unroll
        for (int i = 0; i < 2; i++) {
            int idx = tid + i * 256;
            int r = idx >> 3, c = idx & 7;
            size_t g = bh_off + (size_t)r * DH_ + c * 8;
            uint32_t sw = SMEM_SWZ(r * 128 + c * 16);
            cp16(so + AK + sw, K_ + g);
            cp16(so + AV + sw, V_ + g);
        }
        CP_COMMIT();
    }

    CP_WAIT1();
    __syncthreads();

    const int a_row = wid * 16 + (lane & 15);
    const int a_co = (lane >> 4) * 16;
    uint32_t qh[4][4];
#pragma unroll
    for (int s = 0; s < 4; s++) {
        uint32_t off = SMEM_SWZ(a_row * 128 + s * 32 + a_co);
        ldsm4(qh[s], sb + AQ + off);
    }

    float oa[8][4];
#pragma unroll
    for (int i = 0; i < 8; i++)
#pragma unroll
        for (int j = 0; j < 4; j++) oa[i][j] = 0.f;
    float m0 = -1e30f, m1 = -1e30f, l0 = 0.f, l1 = 0.f;

    const int krow = ((lane >> 4) << 3) + (lane & 7);
    const int kco  = ((lane >> 3) & 1) * 16;
    const int vrow = lane & 15;
    const int vco  = (lane >> 4) * 16;

#pragma unroll 1
    for (int t = 0; t < ntile; t++) {
        CP_WAIT0();
        __syncthreads();
        if (t + 1 < ntile) {
            uint32_t so = sb + AST + ((t + 1) & 1) * AST_BYTES;
            int j0n = (t + 1) * 64;
#pragma unroll
            for (int i = 0; i < 2; i++) {
                int idx = tid + i * 256;
                int r = idx >> 3, c = idx & 7;
                size_t g = bh_off + (size_t)(j0n + r) * DH_ + c * 8;
                uint32_t sw = SMEM_SWZ(r * 128 + c * 16);
                cp16(so + AK + sw, K_ + g);
                cp16(so + AV + sw, V_ + g);
            }
            CP_COMMIT();
        }

        const uint32_t so = sb + AST + (t & 1) * AST_BYTES;
        const int j0 = t * 64;

        // ---- S = Q @ K^T (log2 domain via Q pre-scale) ----
        float S[8][4];
#pragma unroll
        for (int i = 0; i < 8; i++)
#pragma unroll
            for (int j = 0; j < 4; j++) S[i][j] = 0.f;
#pragma unroll
        for (int s = 0; s < 4; s++) {
            uint32_t kh4[4][4];
#pragma unroll
            for (int g = 0; g < 4; g++) {
                uint32_t off = SMEM_SWZ((g * 16 + krow) * 128 + s * 32 + kco);
                ldsm4(kh4[g], so + AK + off);
            }
#pragma unroll
            for (int g = 0; g < 4; g++) {
                mma16816(S[2 * g],     qh[s], kh4[g]);
                mma16816(S[2 * g + 1], qh[s], kh4[g] + 2);
            }
        }

        // ---- mask (partial tiles only) ----
        if (j0 + 64 > len) {
            int kb0 = j0 + 2 * (lane & 3);
#pragma unroll
            for (int j = 0; j < 8; j++) {
#pragma unroll
                for (int e = 0; e < 4; e++) {
                    int kk = kb0 + 8 * j + (e & 1);
                    if (kk >= len) S[j][e] = -1e9f;
                }
            }
        }

        // ---- online softmax (base-2) ----
        float mx0 = -1e30f, mx1 = -1e30f;
#pragma unroll
        for (int j = 0; j < 8; j++) {
            mx0 = fmaxf(mx0, fmaxf(S[j][0], S[j][1]));
            mx1 = fmaxf(mx1, fmaxf(S[j][2], S[j][3]));
        }
        mx0 = fmaxf(mx0, __shfl_xor_sync(0xffffffffu, mx0, 1));
        mx0 = fmaxf(mx0, __shfl_xor_sync(0xffffffffu, mx0, 2));
        mx1 = fmaxf(mx1, __shfl_xor_sync(0xffffffffu, mx1, 1));
        mx1 = fmaxf(mx1, __shfl_xor_sync(0xffffffffu, mx1, 2));
        float mn0 = fmaxf(m0, mx0), mn1 = fmaxf(m1, mx1);
        float f0 = ex2(m0 - mn0), f1 = ex2(m1 - mn1);
        l0 *= f0; l1 *= f1;
#pragma unroll
        for (int i = 0; i < 8; i++) {
            oa[i][0] *= f0; oa[i][1] *= f0; oa[i][2] *= f1; oa[i][3] *= f1;
        }
        float rs0 = 0.f, rs1 = 0.f;
#pragma unroll
        for (int j = 0; j < 8; j++) {
            S[j][0] = ex2(S[j][0] - mn0);
            S[j][1] = ex2(S[j][1] - mn0);
            S[j][2] = ex2(S[j][2] - mn1);
            S[j][3] = ex2(S[j][3] - mn1);
            rs0 += S[j][0] + S[j][1];
            rs1 += S[j][2] + S[j][3];
        }
        rs0 += __shfl_xor_sync(0xffffffffu, rs0, 1);
        rs0 += __shfl_xor_sync(0xffffffffu, rs0, 2);
        rs1 += __shfl_xor_sync(0xffffffffu, rs1, 1);
        rs1 += __shfl_xor_sync(0xffffffffu, rs1, 2);
        l0 += rs0; l1 += rs1;
        m0 = mn0; m1 = mn1;

        // ---- O += P @ V ----
#pragma unroll
        for (int s = 0; s < 4; s++) {
            uint32_t pah[4];
#pragma unroll
            for (int half = 0; half < 2; half++) {
                const float* Sf = S[2 * s + half];
                __half2 hp0 = __floats2half2_rn(Sf[0], Sf[1]);
                __half2 hp1 = __floats2half2_rn(Sf[2], Sf[3]);
                pah[2 * half]     = *(uint32_t*)&hp0;
                pah[2 * half + 1] = *(uint32_t*)&hp1;
            }
            uint32_t vh4[4][4];
#pragma unroll
            for (int g = 0; g < 4; g++) {
                uint32_t off = SMEM_SWZ((s * 16 + vrow) * 128 + g * 32 + vco);
                ldsm4t(vh4[g], so + AV + off);
            }
#pragma unroll
            for (int g = 0; g < 4; g++) {
                mma16816(oa[2 * g],     pah, vh4[g]);
                mma16816(oa[2 * g + 1], pah, vh4[g] + 2);
            }
        }
    }

    // ---- epilogue: normalize, write fp16 row-major [M][D] ----
    float il0 = 1.f / l0, il1 = 1.f / l1;
    int qrow = q0 + wid * 16 + (lane >> 2);
    size_t base0 = ((size_t)b * S_ + qrow) * D_ + h * DH_ + 2 * (lane & 3);
    size_t base1 = base0 + (size_t)8 * D_;
#pragma unroll
    for (int nf = 0; nf < 8; nf++) {
        *(__half2*)(O_ + base0 + 8 * nf) = __floats2half2_rn(oa[nf][0] * il0, oa[nf][1] * il0);
        *(__half2*)(O_ + base1 + 8 * nf) = __floats2half2_rn(oa[nf][2] * il1, oa[nf][3] * il1);
    }
}

// ---------------------------------------------------------------------------
// Combined prep: z 0..3 = weight transpose, z 4..11 = v fp32->fp16.
// grid (32,32,12), block (32,8).
// ---------------------------------------------------------------------------
__global__ __launch_bounds__(256) void prep_kernel(
    const float* __restrict__ W0, const float* __restrict__ W1,
    const float* __restrict__ W2, const float* __restrict__ W3,
    __half* __restrict__ T_,
    const float4* __restrict__ x, __half2* __restrict__ xo)
{
    const int z = blockIdx.z;
    if (z < 4) {
        __shared__ float t[32][33];
        const float* W = (z == 0) ? W0 : (z == 1) ? W1 : (z == 2) ? W2 : W3;
        const int n0 = blockIdx.x * 32, k0 = blockIdx.y * 32;
        const int tx = threadIdx.x, ty = threadIdx.y;
#pragma unroll
        for (int i = 0; i < 4; i++)
            t[ty + i * 8][tx] = W[(size_t)(k0 + ty + i * 8) * D_ + n0 + tx];
        __syncthreads();
#pragma unroll
        for (int i = 0; i < 4; i++) {
            int n = z * D_ + n0 + ty + i * 8;
            T_[(size_t)n * D_ + k0 + tx] = __float2half_rn(t[tx][ty + i * 8]);
        }
    } else {
        int tid = threadIdx.y * 32 + threadIdx.x;
        int blk = (z - 4) * 1024 + blockIdx.y * 32 + blockIdx.x;
        int i = blk * 256 + tid;
        float4 v = x[i];
        xo[2 * i]     = __floats2half2_rn(v.x, v.y);
        xo[2 * i + 1] = __floats2half2_rn(v.z, v.w);
    }
}

// ---------------------------------------------------------------------------
// Launch
// ---------------------------------------------------------------------------
extern "C" void kernel_launch(void* const* d_in, const int* in_sizes, int n_in,
                              void* d_out, int out_size)
{
    (void)in_sizes; (void)n_in; (void)out_size;
    const float* v       = (const float*)d_in[0];
    const int*   lengths = (const int*)  d_in[1];
    const float* Wq      = (const float*)d_in[2];
    const float* bq      = (const float*)d_in[3];
    const float* Wk      = (const float*)d_in[4];
    const float* bk      = (const float*)d_in[5];
    const float* Wv      = (const float*)d_in[6];
    const float* bv      = (const float*)d_in[7];
    const float* Wo      = (const float*)d_in[8];
    const float* bo      = (const float*)d_in[9];
    float* out = (float*)d_out;

    __half *xb, *wb, *qb, *kb, *vb;
    cudaGetSymbolAddress((void**)&xb, g_X);
    cudaGetSymbolAddress((void**)&wb, g_B);
    cudaGetSymbolAddress((void**)&qb, g_Q);
    cudaGetSymbolAddress((void**)&kb, g_K);
    cudaGetSymbolAddress((void**)&vb, g_V);

    cudaFuncSetAttribute(gemm_qkv, cudaFuncAttributeMaxDynamicSharedMemorySize, GEMM_SMEM);
    cudaFuncSetAttribute(gemm_out, cudaFuncAttributeMaxDynamicSharedMemorySize, GEMM_SMEM);
    cudaFuncSetAttribute(attn_mma, cudaFuncAttributeMaxDynamicSharedMemorySize, ATTN_SMEM);

    dim3 gprep(32, 32, 12), bprep(32, 8);
    prep_kernel<<<gprep, bprep>>>(Wq, Wk, Wv, Wo, wb, (const float4*)v, (__half2*)xb);

    dim3 gqkv(3 * D_ / 128, M_ / 128);   // (24, 64)
    gemm_qkv<<<gqkv, 256, GEMM_SMEM>>>(xb, wb, bq, bk, bv, qb, kb, vb, lengths);

    dim3 ga(S_ / 128, H_, B_);           // (4, 16, 16)
    attn_mma<<<ga, 256, ATTN_SMEM>>>(qb, kb, vb, lengths, xb);

    dim3 go(D_ / 128, M_ / 128);         // (8, 64)
    gemm_out<<<go, 256, GEMM_SMEM>>>(xb, wb + (size_t)3 * D_ * D_, bo, out);
}